// round 6
// baseline (speedup 1.0000x reference)
#include <cuda_runtime.h>
#include <cstdint>

#define NN 100000
#define EE 1600000
#define FEA 128
#define HH 64
#define GGRAPH 512
#define NL 4
#define BN_EPS 1e-5f
#define NTILE 782      // ceil(NN/128)
#define NCH 391        // ceil(NN/256)
#define ECH 6250       // EE/256
#define GRP16 6250     // NN/16 (exact)

// ---------------- scratch ----------------
__device__ float g_tA[(size_t)NN * HH];
__device__ float g_tB[(size_t)NN * HH];
__device__ float g_z[(size_t)NN * HH];
__device__ float g_stats[10 * 128];
__device__ float g_pooled[(NL + 1) * GGRAPH * HH];
__device__ int   g_cnt[GGRAPH];
__device__ int   g_deg[NN];
__device__ int   g_cur[NN];
__device__ int   g_off[NN + 1];
__device__ int   g_bsum[NCH];
__device__ int   g_csr[EE];
__device__ int   g_barcnt;
__device__ volatile int g_bargen;
__device__ int   g_tix[32];

// smem layout (bytes)
#define SM_AS 0            // 128*36 u32 = 18432
#define SM_BS 18432        // 32*72 u32  = 9216
#define SM_SW 27648        // 8*128 f    = 4096
#define SM_AB 31744        // 128 f      = 512
#define SM_SCR 32256       // 512 int    = 2048
#define SM_BYTES 34304

__device__ __forceinline__ void red_add_v4(float* p, float4 v) {
    asm volatile("red.global.add.v4.f32 [%0], {%1,%2,%3,%4};"
                 :: "l"(p), "f"(v.x), "f"(v.y), "f"(v.z), "f"(v.w) : "memory");
}
__device__ __forceinline__ uint32_t f2tf32(float f) {
    uint32_t r;
    asm("cvt.rna.tf32.f32 %0, %1;" : "=r"(r) : "f"(f));
    return r;
}
__device__ __forceinline__ void mma_tf32(float& c0, float& c1, float& c2, float& c3,
                                         uint32_t a0, uint32_t a1, uint32_t a2, uint32_t a3,
                                         uint32_t b0, uint32_t b1) {
    asm volatile("mma.sync.aligned.m16n8k8.row.col.f32.tf32.tf32.f32 "
                 "{%0,%1,%2,%3}, {%4,%5,%6,%7}, {%8,%9}, {%0,%1,%2,%3};"
                 : "+f"(c0), "+f"(c1), "+f"(c2), "+f"(c3)
                 : "r"(a0), "r"(a1), "r"(a2), "r"(a3), "r"(b0), "r"(b1));
}

// device-wide barrier (all blocks resident). fence.gpu -> L1 invalidate.
__device__ __forceinline__ void gbar() {
    __syncthreads();
    __threadfence();
    if (threadIdx.x == 0) {
        int gen = g_bargen;
        if (atomicAdd(&g_barcnt, 1) == (int)gridDim.x - 1) {
            g_barcnt = 0;
            __threadfence();
            g_bargen = gen + 1;
        } else {
            while (g_bargen == gen) __nanosleep(64);
        }
    }
    __syncthreads();
    __threadfence();
}

__device__ __forceinline__ int next_item(int ph) {
    __shared__ int s_it;
    __syncthreads();
    if (threadIdx.x == 0) s_it = atomicAdd(&g_tix[ph], 1);
    __syncthreads();
    return s_it;
}

// derive folded BN affine [a(64), c(64)] for stage st into smem ab
__device__ void make_ab(uint8_t* sm, int st, const float* __restrict__ gamma,
                        const float* __restrict__ beta) {
    float* ab = (float*)(sm + SM_AB);
    int tid = threadIdx.x;
    if (tid < 64) {
        float s = g_stats[st * 128 + tid];
        float q = g_stats[st * 128 + 64 + tid];
        float m = s * (1.f / NN);
        float v = q * (1.f / NN) - m * m;
        float a = gamma[tid] * rsqrtf(v + BN_EPS);
        ab[tid] = a;
        ab[64 + tid] = beta[tid] - a * m;
    }
    __syncthreads();
}

// ---------------- one 128x64 tf32 GEMM tile + fused stats ----------------
__device__ void gemm_tile(uint8_t* sm, int tile, const float* __restrict__ A, int K,
                          const float* __restrict__ W, const float* __restrict__ bias,
                          bool use_trans, float* __restrict__ Y, float* __restrict__ stats)
{
    uint32_t* As_u = (uint32_t*)(sm + SM_AS);
    uint32_t* Bs_u = (uint32_t*)(sm + SM_BS);
    float*    sw   = (float*)(sm + SM_SW);
    const float* trans = (const float*)(sm + SM_AB);

    int tid = threadIdx.x;
    int wid = tid >> 5, lane = tid & 31;
    int g = lane >> 2, tig = lane & 3;
    int row0 = tile * 128;
    int wr0 = wid * 16;

    float c[8][4];
#pragma unroll
    for (int j = 0; j < 8; j++)
#pragma unroll
        for (int q = 0; q < 4; q++) c[j][q] = 0.f;

    const int nchunk = K >> 5;
    for (int ch = 0; ch < nchunk; ch++) {
        int k0 = ch * 32;
#pragma unroll
        for (int i = 0; i < 4; i++) {
            int li = tid + i * 256;
            int r = li >> 3, c4 = li & 7;
            int grow = row0 + r;
            float4 v = make_float4(0.f, 0.f, 0.f, 0.f);
            if (grow < NN) v = *(const float4*)(A + (size_t)grow * K + k0 + c4 * 4);
            if (use_trans) {
                int kb = k0 + c4 * 4;
                v.x = fmaxf(0.f, trans[kb + 0] * v.x + trans[64 + kb + 0]);
                v.y = fmaxf(0.f, trans[kb + 1] * v.y + trans[64 + kb + 1]);
                v.z = fmaxf(0.f, trans[kb + 2] * v.z + trans[64 + kb + 2]);
                v.w = fmaxf(0.f, trans[kb + 3] * v.w + trans[64 + kb + 3]);
            }
            uint4 u;
            u.x = f2tf32(v.x); u.y = f2tf32(v.y); u.z = f2tf32(v.z); u.w = f2tf32(v.w);
            *(uint4*)(&As_u[r * 36 + c4 * 4]) = u;
        }
#pragma unroll
        for (int i = 0; i < 2; i++) {
            int li = tid + i * 256;
            int kr = li >> 4, n4 = li & 15;
            float4 w = *(const float4*)(W + (size_t)(k0 + kr) * 64 + n4 * 4);
            uint4 u;
            u.x = f2tf32(w.x); u.y = f2tf32(w.y); u.z = f2tf32(w.z); u.w = f2tf32(w.w);
            *(uint4*)(&Bs_u[kr * 72 + n4 * 4]) = u;
        }
        __syncthreads();
#pragma unroll
        for (int s = 0; s < 4; s++) {
            int k8 = s * 8;
            uint32_t a0 = As_u[(wr0 + g) * 36 + k8 + tig];
            uint32_t a1 = As_u[(wr0 + g + 8) * 36 + k8 + tig];
            uint32_t a2 = As_u[(wr0 + g) * 36 + k8 + tig + 4];
            uint32_t a3 = As_u[(wr0 + g + 8) * 36 + k8 + tig + 4];
#pragma unroll
            for (int j = 0; j < 8; j++) {
                uint32_t b0 = Bs_u[(k8 + tig) * 72 + j * 8 + g];
                uint32_t b1 = Bs_u[(k8 + tig + 4) * 72 + j * 8 + g];
                mma_tf32(c[j][0], c[j][1], c[j][2], c[j][3], a0, a1, a2, a3, b0, b1);
            }
        }
        __syncthreads();
    }

    int rlo = row0 + wr0 + g;
    int rhi = rlo + 8;
    bool vlo = rlo < NN, vhi = rhi < NN;
#pragma unroll
    for (int j = 0; j < 8; j++) {
        int e0 = j * 8 + 2 * tig;
        float b0 = bias[e0], b1 = bias[e0 + 1];
        float y00 = c[j][0] + b0, y01 = c[j][1] + b1;
        float y10 = c[j][2] + b0, y11 = c[j][3] + b1;
        if (vlo) *(float2*)(Y + (size_t)rlo * 64 + e0) = make_float2(y00, y01);
        if (vhi) *(float2*)(Y + (size_t)rhi * 64 + e0) = make_float2(y10, y11);
        float s0 = (vlo ? y00 : 0.f) + (vhi ? y10 : 0.f);
        float s1 = (vlo ? y01 : 0.f) + (vhi ? y11 : 0.f);
        float q0 = (vlo ? y00 * y00 : 0.f) + (vhi ? y10 * y10 : 0.f);
        float q1 = (vlo ? y01 * y01 : 0.f) + (vhi ? y11 * y11 : 0.f);
#pragma unroll
        for (int m = 4; m <= 16; m <<= 1) {
            s0 += __shfl_xor_sync(0xffffffffu, s0, m);
            s1 += __shfl_xor_sync(0xffffffffu, s1, m);
            q0 += __shfl_xor_sync(0xffffffffu, q0, m);
            q1 += __shfl_xor_sync(0xffffffffu, q1, m);
        }
        if (g == 0) {
            sw[wid * 128 + e0] = s0;
            sw[wid * 128 + e0 + 1] = s1;
            sw[wid * 128 + 64 + e0] = q0;
            sw[wid * 128 + 64 + e0 + 1] = q1;
        }
    }
    __syncthreads();
    if (tid < 128) {
        float tot = 0.f;
#pragma unroll
        for (int w = 0; w < 8; w++) tot += sw[w * 128 + tid];
        atomicAdd(&stats[tid], tot);
    }
}

// scan of 256 degrees (chunk c), writes within-chunk prefix + chunk total
__device__ void scan_chunk(uint8_t* sm, int c) {
    int* s = (int*)(sm + SM_SCR);
    int tid = threadIdx.x;
    int i = c * 256 + tid;
    int v = (i < NN) ? g_deg[i] : 0;
    s[tid] = v;
    __syncthreads();
    for (int off = 1; off < 256; off <<= 1) {
        int t = (tid >= off) ? s[tid - off] : 0;
        __syncthreads();
        s[tid] += t;
        __syncthreads();
    }
    if (i <= NN) g_off[i] = s[tid] - v;
    if (tid == 255) g_bsum[c] = s[255];
    __syncthreads();
}

// ---------------- phase drivers ----------------
__device__ void ph_gemm(int ph, uint8_t* sm, const float* A, int K,
                        const float* W, const float* bias,
                        int tst, const float* tg, const float* tb,
                        float* Y, float* stats, int extra,
                        const int* __restrict__ edge, const int* __restrict__ batch)
{
    if (tst >= 0) make_ab(sm, tst, tg, tb);
    int TOT = NTILE + (extra == 1 ? ECH : (extra == 2 ? NCH : 0));
    for (;;) {
        int it = next_item(ph);
        if (it >= TOT) break;
        if (it < NTILE) {
            gemm_tile(sm, it, A, K, W, bias, tst >= 0, Y, stats);
        } else if (extra == 1) {
            int idx = (it - NTILE) * 256 + threadIdx.x;
            if (idx < EE) atomicAdd(&g_deg[edge[EE + idx]], 1);
            if (idx < NN) atomicAdd(&g_cnt[batch[idx]], 1);
        } else {
            scan_chunk(sm, it - NTILE);
        }
    }
}

__device__ void ph_addtop(int ph, uint8_t* sm) {
    int* s = (int*)(sm + SM_SCR);
    int tid = threadIdx.x;
    for (;;) {
        int c = next_item(ph);
        if (c >= NCH) break;
        int partial = 0;
        if (tid < c) partial += g_bsum[tid];
        if (tid + 256 < c) partial += g_bsum[tid + 256];
        s[tid] = partial;
        __syncthreads();
        for (int off = 128; off > 0; off >>= 1) {
            if (tid < off) s[tid] += s[tid + off];
            __syncthreads();
        }
        int base = s[0];
        __syncthreads();
        int i = c * 256 + tid;
        if (i <= NN) g_off[i] += base;
    }
}

__device__ void ph_fill(int ph, const int* __restrict__ edge) {
    for (;;) {
        int ci = next_item(ph);
        if (ci >= ECH) break;
        int e = ci * 256 + threadIdx.x;   // always < EE
        int d = edge[EE + e];
        int pos = g_off[d] + atomicAdd(&g_cur[d], 1);
        g_csr[pos] = edge[e];
    }
}

// gather (optional) + segmented pooling, both on relu(a*tB+c)
__device__ void ph_gather(int ph, uint8_t* sm, int st,
                          const float* __restrict__ gamma, const float* __restrict__ beta,
                          int level, const int* __restrict__ batch, bool do_gather)
{
    make_ab(sm, st, gamma, beta);
    float* ab = (float*)(sm + SM_AB);
    float4* su = (float4*)(sm);                 // 16 x 17 float4
    int* sb = (int*)(sm + 16 * 17 * 16);
    int tid = threadIdx.x;
    int rl = tid >> 4, l16 = tid & 15, cc = l16 * 4;
    float a0 = ab[cc + 0], a1 = ab[cc + 1], a2 = ab[cc + 2], a3 = ab[cc + 3];
    float o0 = ab[64 + cc + 0], o1 = ab[64 + cc + 1], o2 = ab[64 + cc + 2], o3 = ab[64 + cc + 3];
    float* pooled = g_pooled + (size_t)level * GGRAPH * HH;

    for (;;) {
        int it = next_item(ph);
        if (it >= GRP16) break;
        int node = it * 16 + rl;                 // always < NN (NN = GRP16*16)
        float4 t = *(const float4*)(g_tB + (size_t)node * 64 + cc);
        float4 u;
        u.x = fmaxf(0.f, a0 * t.x + o0);
        u.y = fmaxf(0.f, a1 * t.y + o1);
        u.z = fmaxf(0.f, a2 * t.z + o2);
        u.w = fmaxf(0.f, a3 * t.w + o3);
        int b = batch[node];
        if (l16 == 0) sb[rl] = b;
        su[rl * 17 + l16] = u;
        __syncthreads();
        bool head = (rl == 0) || (b != sb[rl - 1]);
        if (head) {
            float4 acc2 = u;
            for (int k2 = rl + 1; k2 < 16 && sb[k2] == b; k2++) {
                float4 w = su[k2 * 17 + l16];
                acc2.x += w.x; acc2.y += w.y; acc2.z += w.z; acc2.w += w.w;
            }
            red_add_v4(pooled + (size_t)b * 64 + cc, acc2);
        }
        if (do_gather) {
            int off0 = g_off[node];
            int cnt = g_off[node + 1] - off0;
            float4 acc = u;
            int vmax = cnt;
#pragma unroll
            for (int sft = 16; sft > 0; sft >>= 1)
                vmax = max(vmax, __shfl_xor_sync(0xffffffffu, vmax, sft));
            for (int base = 0; base < vmax; base += 16) {
                int myidx = (base + l16 < cnt) ? g_csr[off0 + base + l16] : -1;
#pragma unroll
                for (int j = 0; j < 16; j++) {
                    int idx = __shfl_sync(0xffffffffu, myidx, j, 16);
                    if (idx >= 0) {
                        float4 v = *(const float4*)(g_tB + (size_t)idx * 64 + cc);
                        acc.x += fmaxf(0.f, a0 * v.x + o0);
                        acc.y += fmaxf(0.f, a1 * v.y + o1);
                        acc.z += fmaxf(0.f, a2 * v.z + o2);
                        acc.w += fmaxf(0.f, a3 * v.w + o3);
                    }
                }
            }
            *(float4*)(g_z + (size_t)node * 64 + cc) = acc;
        }
        __syncthreads();
    }
}

__device__ void ph_out(int ph, uint8_t* sm, const float* __restrict__ linW,
                       const float* __restrict__ linb, float* __restrict__ out)
{
    float* ps = (float*)(sm);    // 4 graphs x 320 floats
    int tid = threadIdx.x;
    int sub = tid >> 6, t = tid & 63;
    for (;;) {
        int it = next_item(ph);
        if (it >= GGRAPH / 4) break;
        int g = it * 4 + sub;
        float* mp = ps + sub * 320;
        for (int i = t; i < 320; i += 64) {
            int l = i >> 6, j = i & 63;
            mp[i] = g_pooled[(size_t)l * GGRAPH * 64 + (size_t)g * 64 + j];
        }
        __syncthreads();
        float acc = (float)g_cnt[g] * linb[t];
#pragma unroll
        for (int l = 1; l < NL + 1; l++) acc += linb[l * 64 + t];
        for (int l = 0; l < NL + 1; l++) {
            const float* wl = linW + (size_t)l * 64 * 64;
            const float* pl = mp + l * 64;
#pragma unroll 8
            for (int j = 0; j < 64; j++) acc += pl[j] * wl[j * 64 + t];
        }
        out[(size_t)g * 64 + t] = acc;
        __syncthreads();
    }
}

// ---------------- zero ----------------
__global__ void zero_kernel() {
    int i = blockIdx.x * blockDim.x + threadIdx.x;
    int STR = gridDim.x * blockDim.x;
    for (int k = i; k < (NL + 1) * GGRAPH * HH; k += STR) g_pooled[k] = 0.f;
    for (int k = i; k < NN; k += STR) { g_deg[k] = 0; g_cur[k] = 0; }
    if (i < 10 * 128) g_stats[i] = 0.f;
    if (i < GGRAPH) g_cnt[i] = 0;
    if (i < 32) g_tix[i] = 0;
    if (i == 0) { g_barcnt = 0; g_bargen = 0; }
}

// ---------------- the megakernel ----------------
__global__ __launch_bounds__(256, 2) void mega(
    const float* x, const int* edge, const int* batch,
    const float* fW1, const float* fb1, const float* fg1, const float* fbt1,
    const float* fW2, const float* fb2, const float* fg2, const float* fbt2,
    const float* cW1, const float* cb1, const float* cg1, const float* cbt1,
    const float* cW2, const float* cb2, const float* cg2, const float* cbt2,
    const float* linW, const float* linb, float* out)
{
    __shared__ __align__(16) uint8_t sm[SM_BYTES];

    // P0: GEMM stage0 (x @ fW1) || degree+graph histograms
    ph_gemm(0, sm, x, FEA, fW1, fb1, -1, nullptr, nullptr, g_tA, g_stats + 0, 1, edge, batch);
    gbar();
    // P1: GEMM stage1 (relu(ab0∘tA) @ fW2) || per-chunk degree scan
    ph_gemm(1, sm, g_tA, HH, fW2, fb2, 0, fg1, fbt1, g_tB, g_stats + 128, 2, edge, batch);
    gbar();
    // P2: chunk-base add
    ph_addtop(2, sm);
    gbar();
    // P3: CSR fill
    ph_fill(3, edge);
    gbar();

    for (int l = 0; l < NL; l++) {
        int st = 2 * l + 1;
        const float* gA = (l == 0) ? fg2 : cg2 + (size_t)(l - 1) * HH;
        const float* bA = (l == 0) ? fbt2 : cbt2 + (size_t)(l - 1) * HH;
        int sA = 2 + 2 * l, sB = 3 + 2 * l;
        // gather + pool level l (reads tB stage st)
        ph_gather(4 + 3 * l, sm, st, gA, bA, l, batch, true);
        gbar();
        // GEMM sA: z @ cW1[l]
        ph_gemm(5 + 3 * l, sm, g_z, HH, cW1 + (size_t)l * HH * HH, cb1 + (size_t)l * HH,
                -1, nullptr, nullptr, g_tA, g_stats + sA * 128, 0, edge, batch);
        gbar();
        // GEMM sB: relu(ab_sA∘tA) @ cW2[l]
        ph_gemm(6 + 3 * l, sm, g_tA, HH, cW2 + (size_t)l * HH * HH, cb2 + (size_t)l * HH,
                sA, cg1 + (size_t)l * HH, cbt1 + (size_t)l * HH,
                g_tB, g_stats + sB * 128, 0, edge, batch);
        gbar();
    }
    // pool level NL (stage 9), no gather
    ph_gather(16, sm, 9, cg2 + (size_t)3 * HH, cbt2 + (size_t)3 * HH, NL, batch, false);
    gbar();
    // readout
    ph_out(17, sm, linW, linb, out);
}

// ---------------- launch ----------------
extern "C" void kernel_launch(void* const* d_in, const int* in_sizes, int n_in,
                              void* d_out, int out_size)
{
    const float* x    = (const float*)d_in[0];
    const int*  edge  = (const int*)d_in[1];
    const int*  batch = (const int*)d_in[2];
    const float* fW1 = (const float*)d_in[3];
    const float* fb1 = (const float*)d_in[4];
    const float* fg1 = (const float*)d_in[5];
    const float* fbt1= (const float*)d_in[6];
    const float* fW2 = (const float*)d_in[7];
    const float* fb2 = (const float*)d_in[8];
    const float* fg2 = (const float*)d_in[9];
    const float* fbt2= (const float*)d_in[10];
    const float* cW1 = (const float*)d_in[11];
    const float* cb1 = (const float*)d_in[12];
    const float* cg1 = (const float*)d_in[13];
    const float* cbt1= (const float*)d_in[14];
    const float* cW2 = (const float*)d_in[15];
    const float* cb2 = (const float*)d_in[16];
    const float* cg2 = (const float*)d_in[17];
    const float* cbt2= (const float*)d_in[18];
    const float* linW= (const float*)d_in[19];
    const float* linb= (const float*)d_in[20];

    int smCount = 0;
    cudaDeviceGetAttribute(&smCount, cudaDevAttrMultiProcessorCount, 0);
    int occ = 0;
    cudaOccupancyMaxActiveBlocksPerMultiprocessor(&occ, mega, 256, 0);
    if (occ < 1) occ = 1;
    if (occ > 2) occ = 2;
    int G = smCount * occ;

    zero_kernel<<<640, 256>>>();
    mega<<<G, 256>>>(x, edge, batch,
                     fW1, fb1, fg1, fbt1, fW2, fb2, fg2, fbt2,
                     cW1, cb1, cg1, cbt1, cW2, cb2, cg2, cbt2,
                     linW, linb, (float*)d_out);
}

// round 8
// speedup vs baseline: 1.2750x; 1.2750x over previous
#include <cuda_runtime.h>
#include <cstdint>

#define NN 100000
#define EE 1600000
#define FEADIM 128
#define HH 64
#define GG 512
#define NLAYERS 4
#define BN_EPS 1e-5f
#define SCAN_NBLK 98   // ceil((NN+1)/1024)
#define GEMM_BLOCKS ((NN + 127) / 128)   // 782

// ---------------- scratch ----------------
__device__ float g_tA[(size_t)NN * HH];
__device__ float g_tB[(size_t)NN * HH];
__device__ float g_stats[10 * 128];
__device__ float g_ab[10 * 128];
__device__ float g_pooled[(NLAYERS + 1) * GG * HH];
__device__ int   g_cnt[GG];
__device__ int   g_deg[NN];
__device__ int   g_cur[NN];
__device__ int   g_off[NN + 1];
__device__ int   g_bsum[SCAN_NBLK];
__device__ int   g_bsum2[SCAN_NBLK];
__device__ int   g_csr[EE];
__device__ int   g_done[16];

__device__ __forceinline__ void red_add_v4(float* p, float4 v) {
    asm volatile("red.global.add.v4.f32 [%0], {%1,%2,%3,%4};"
                 :: "l"(p), "f"(v.x), "f"(v.y), "f"(v.z), "f"(v.w) : "memory");
}
__device__ __forceinline__ uint32_t f2tf32(float f) {
    uint32_t r;
    asm("cvt.rna.tf32.f32 %0, %1;" : "=r"(r) : "f"(f));
    return r;
}
__device__ __forceinline__ void mma_tf32(float& c0, float& c1, float& c2, float& c3,
                                         uint32_t a0, uint32_t a1, uint32_t a2, uint32_t a3,
                                         uint32_t b0, uint32_t b1) {
    asm volatile("mma.sync.aligned.m16n8k8.row.col.f32.tf32.tf32.f32 "
                 "{%0,%1,%2,%3}, {%4,%5,%6,%7}, {%8,%9}, {%0,%1,%2,%3};"
                 : "+f"(c0), "+f"(c1), "+f"(c2), "+f"(c3)
                 : "r"(a0), "r"(a1), "r"(a2), "r"(a3), "r"(b0), "r"(b1));
}

// ---------------- setup kernels ----------------

__global__ void zero_kernel() {
    const int TOT = (NLAYERS + 1) * GG * HH;
    for (int i = blockIdx.x * blockDim.x + threadIdx.x; i < TOT;
         i += gridDim.x * blockDim.x) {
        g_pooled[i] = 0.f;
        if (i < NN) { g_deg[i] = 0; g_cur[i] = 0; }
        if (i < 10 * 128) g_stats[i] = 0.f;
        if (i < GG) g_cnt[i] = 0;
        if (i < 16) g_done[i] = 0;
    }
}

__global__ void count_kernel(const int* __restrict__ edge, const int* __restrict__ batch) {
    int i = blockIdx.x * blockDim.x + threadIdx.x;
    if (i < EE) atomicAdd(&g_deg[edge[EE + i]], 1);
    if (i < NN) atomicAdd(&g_cnt[batch[i]], 1);
}

__global__ void scan_block_kernel() {
    __shared__ int s[1024];
    int tid = threadIdx.x;
    int i = blockIdx.x * 1024 + tid;
    int v = (i < NN) ? g_deg[i] : 0;
    s[tid] = v;
    __syncthreads();
    for (int off = 1; off < 1024; off <<= 1) {
        int t = (tid >= off) ? s[tid - off] : 0;
        __syncthreads();
        s[tid] += t;
        __syncthreads();
    }
    if (i <= NN) g_off[i] = s[tid] - v;
    if (tid == 1023) g_bsum[blockIdx.x] = s[1023];
}

__global__ void scan_top_kernel() {
    __shared__ int s[128];
    int tid = threadIdx.x;
    int v = (tid < SCAN_NBLK) ? g_bsum[tid] : 0;
    s[tid] = v;
    __syncthreads();
    for (int off = 1; off < 128; off <<= 1) {
        int t = (tid >= off) ? s[tid - off] : 0;
        __syncthreads();
        s[tid] += t;
        __syncthreads();
    }
    if (tid < SCAN_NBLK) g_bsum2[tid] = s[tid] - v;
}

__global__ void scan_add_kernel() {
    int i = blockIdx.x * 1024 + threadIdx.x;
    if (i <= NN) g_off[i] += g_bsum2[i >> 10];
}

__global__ void fill_csr_kernel(const int* __restrict__ edge) {
    int e = blockIdx.x * blockDim.x + threadIdx.x;
    if (e >= EE) return;
    int d = edge[EE + e];
    int pos = g_off[d] + atomicAdd(&g_cur[d], 1);
    g_csr[pos] = edge[e];
}

// ---------------- tf32 GEMM + fused BN stats & finalize ----------------
__global__ __launch_bounds__(256) void gemm_tc_kernel(
    const float* __restrict__ Aext, int Asel, int K,
    const float* __restrict__ W, const float* __restrict__ bias,
    int tstage, int Ysel, int sstage,
    const float* __restrict__ gamma, const float* __restrict__ beta)
{
    const float* A = (Asel == 0) ? Aext : g_tA;
    float* Y = (Ysel == 0) ? g_tA : g_tB;
    const float* trans = (tstage >= 0) ? (g_ab + tstage * 128) : nullptr;
    float* stats = g_stats + sstage * 128;

    __shared__ uint32_t As_u[128 * 36];
    __shared__ uint32_t Bs_u[32 * 72];
    __shared__ float    sw[8 * 128];
    __shared__ bool     slast;

    int tid = threadIdx.x;
    int wid = tid >> 5, lane = tid & 31;
    int g = lane >> 2, tig = lane & 3;
    int row0 = blockIdx.x * 128;
    int wr0 = wid * 16;

    float c[8][4];
#pragma unroll
    for (int j = 0; j < 8; j++)
#pragma unroll
        for (int q = 0; q < 4; q++) c[j][q] = 0.f;

    const int nchunk = K >> 5;
    for (int ch = 0; ch < nchunk; ch++) {
        int k0 = ch * 32;
#pragma unroll
        for (int i = 0; i < 4; i++) {
            int li = tid + i * 256;
            int r = li >> 3, c4 = li & 7;
            int grow = row0 + r;
            float4 v = make_float4(0.f, 0.f, 0.f, 0.f);
            if (grow < NN) v = *(const float4*)(A + (size_t)grow * K + k0 + c4 * 4);
            if (trans) {
                int kb = k0 + c4 * 4;
                v.x = fmaxf(0.f, trans[kb + 0] * v.x + trans[64 + kb + 0]);
                v.y = fmaxf(0.f, trans[kb + 1] * v.y + trans[64 + kb + 1]);
                v.z = fmaxf(0.f, trans[kb + 2] * v.z + trans[64 + kb + 2]);
                v.w = fmaxf(0.f, trans[kb + 3] * v.w + trans[64 + kb + 3]);
            }
            uint4 u;
            u.x = f2tf32(v.x); u.y = f2tf32(v.y); u.z = f2tf32(v.z); u.w = f2tf32(v.w);
            *(uint4*)(&As_u[r * 36 + c4 * 4]) = u;
        }
#pragma unroll
        for (int i = 0; i < 2; i++) {
            int li = tid + i * 256;
            int kr = li >> 4, n4 = li & 15;
            float4 w = *(const float4*)(W + (size_t)(k0 + kr) * 64 + n4 * 4);
            uint4 u;
            u.x = f2tf32(w.x); u.y = f2tf32(w.y); u.z = f2tf32(w.z); u.w = f2tf32(w.w);
            *(uint4*)(&Bs_u[kr * 72 + n4 * 4]) = u;
        }
        __syncthreads();
#pragma unroll
        for (int s = 0; s < 4; s++) {
            int k8 = s * 8;
            uint32_t a0 = As_u[(wr0 + g) * 36 + k8 + tig];
            uint32_t a1 = As_u[(wr0 + g + 8) * 36 + k8 + tig];
            uint32_t a2 = As_u[(wr0 + g) * 36 + k8 + tig + 4];
            uint32_t a3 = As_u[(wr0 + g + 8) * 36 + k8 + tig + 4];
#pragma unroll
            for (int j = 0; j < 8; j++) {
                uint32_t b0 = Bs_u[(k8 + tig) * 72 + j * 8 + g];
                uint32_t b1 = Bs_u[(k8 + tig + 4) * 72 + j * 8 + g];
                mma_tf32(c[j][0], c[j][1], c[j][2], c[j][3], a0, a1, a2, a3, b0, b1);
            }
        }
        __syncthreads();
    }

    int rlo = row0 + wr0 + g;
    int rhi = rlo + 8;
    bool vlo = rlo < NN, vhi = rhi < NN;
#pragma unroll
    for (int j = 0; j < 8; j++) {
        int e0 = j * 8 + 2 * tig;
        float b0 = bias[e0], b1 = bias[e0 + 1];
        float y00 = c[j][0] + b0, y01 = c[j][1] + b1;
        float y10 = c[j][2] + b0, y11 = c[j][3] + b1;
        if (vlo) *(float2*)(Y + (size_t)rlo * 64 + e0) = make_float2(y00, y01);
        if (vhi) *(float2*)(Y + (size_t)rhi * 64 + e0) = make_float2(y10, y11);
        float s0 = (vlo ? y00 : 0.f) + (vhi ? y10 : 0.f);
        float s1 = (vlo ? y01 : 0.f) + (vhi ? y11 : 0.f);
        float q0 = (vlo ? y00 * y00 : 0.f) + (vhi ? y10 * y10 : 0.f);
        float q1 = (vlo ? y01 * y01 : 0.f) + (vhi ? y11 * y11 : 0.f);
#pragma unroll
        for (int m = 4; m <= 16; m <<= 1) {
            s0 += __shfl_xor_sync(0xffffffffu, s0, m);
            s1 += __shfl_xor_sync(0xffffffffu, s1, m);
            q0 += __shfl_xor_sync(0xffffffffu, q0, m);
            q1 += __shfl_xor_sync(0xffffffffu, q1, m);
        }
        if (g == 0) {
            sw[wid * 128 + e0] = s0;
            sw[wid * 128 + e0 + 1] = s1;
            sw[wid * 128 + 64 + e0] = q0;
            sw[wid * 128 + 64 + e0 + 1] = q1;
        }
    }
    __syncthreads();
    if (tid < 128) {
        float tot = 0.f;
#pragma unroll
        for (int w = 0; w < 8; w++) tot += sw[w * 128 + tid];
        atomicAdd(&stats[tid], tot);
        __threadfence();
    }
    __syncthreads();
    if (tid == 0) {
        int v = atomicAdd(&g_done[sstage], 1);
        slast = (v == (int)gridDim.x - 1);
    }
    __syncthreads();
    if (slast && tid < 64) {
        float s_ = __ldcg(&stats[tid]);
        float q_ = __ldcg(&stats[64 + tid]);
        float m = s_ * (1.f / NN);
        float var = q_ * (1.f / NN) - m * m;
        float a = gamma[tid] * rsqrtf(var + BN_EPS);
        g_ab[sstage * 128 + tid] = a;
        g_ab[sstage * 128 + 64 + tid] = beta[tid] - a * m;
    }
}

// ---------------- fused: gather + pooling(level) + conv GEMM sA ----------------
#define FS_AS 0
#define FS_BS (128 * 68 * 4)                        // 34816
#define FS_SW (FS_BS + 64 * 72 * 4)                 // 53248
#define FS_SU (FS_SW + 8 * 128 * 4)                 // 57344
#define FS_SB (FS_SU + 16 * 17 * 16)                // 61696
#define FS_BYTES (FS_SB + 64 + 64)                  // 61824

__global__ __launch_bounds__(256) void gin_fused_kernel(
    int tst, int level, const int* __restrict__ batch,
    const float* __restrict__ W, const float* __restrict__ bias,
    int sstage, const float* __restrict__ gamma, const float* __restrict__ beta)
{
    extern __shared__ __align__(16) uint8_t smraw[];
    uint32_t* As_u = (uint32_t*)(smraw + FS_AS);
    uint32_t* Bs_u = (uint32_t*)(smraw + FS_BS);
    float*    sw   = (float*)(smraw + FS_SW);
    float4*   su   = (float4*)(smraw + FS_SU);
    int*      sb   = (int*)(smraw + FS_SB);
    __shared__ bool slast;

    const float* ab = g_ab + tst * 128;
    float* pooled = g_pooled + (size_t)level * GG * HH;
    float* stats = g_stats + sstage * 128;

    int tid = threadIdx.x;
    int rl = tid >> 4, l16 = tid & 15, cc = l16 * 4;
    int row0 = blockIdx.x * 128;

    float a0 = ab[cc + 0], a1 = ab[cc + 1], a2 = ab[cc + 2], a3 = ab[cc + 3];
    float o0 = ab[64 + cc], o1 = ab[64 + cc + 1], o2 = ab[64 + cc + 2], o3 = ab[64 + cc + 3];

    // ---- phase 1: 8 passes of 16 nodes: activate, pool, gather, stash tf32 row ----
    for (int p = 0; p < 8; p++) {
        int lrow = p * 16 + rl;
        int node = row0 + lrow;
        bool valid = node < NN;
        float4 u = make_float4(0.f, 0.f, 0.f, 0.f);
        int b = -1;
        if (valid) {
            float4 t = *(const float4*)(g_tB + (size_t)node * 64 + cc);
            u.x = fmaxf(0.f, a0 * t.x + o0);
            u.y = fmaxf(0.f, a1 * t.y + o1);
            u.z = fmaxf(0.f, a2 * t.z + o2);
            u.w = fmaxf(0.f, a3 * t.w + o3);
            b = batch[node];
        }
        if (l16 == 0) sb[rl] = b;
        su[rl * 17 + l16] = u;
        __syncthreads();
        if (valid) {
            bool head = (rl == 0) || (b != sb[rl - 1]);
            if (head) {
                float4 acc2 = u;
                for (int k2 = rl + 1; k2 < 16 && sb[k2] == b; k2++) {
                    float4 w = su[k2 * 17 + l16];
                    acc2.x += w.x; acc2.y += w.y; acc2.z += w.z; acc2.w += w.w;
                }
                red_add_v4(pooled + (size_t)b * 64 + cc, acc2);
            }
        }
        // gather neighbors
        float4 acc = u;
        int off0 = 0, cnt = 0;
        if (valid) { off0 = g_off[node]; cnt = g_off[node + 1] - off0; }
        int vmax = cnt;
#pragma unroll
        for (int sft = 16; sft > 0; sft >>= 1)
            vmax = max(vmax, __shfl_xor_sync(0xffffffffu, vmax, sft));
        for (int base = 0; base < vmax; base += 16) {
            int myidx = (base + l16 < cnt) ? g_csr[off0 + base + l16] : -1;
#pragma unroll
            for (int j = 0; j < 16; j++) {
                int idx = __shfl_sync(0xffffffffu, myidx, j, 16);
                if (idx >= 0) {
                    float4 v = *(const float4*)(g_tB + (size_t)idx * 64 + cc);
                    acc.x += fmaxf(0.f, a0 * v.x + o0);
                    acc.y += fmaxf(0.f, a1 * v.y + o1);
                    acc.z += fmaxf(0.f, a2 * v.z + o2);
                    acc.w += fmaxf(0.f, a3 * v.w + o3);
                }
            }
        }
        uint4 uu;
        uu.x = f2tf32(acc.x); uu.y = f2tf32(acc.y); uu.z = f2tf32(acc.z); uu.w = f2tf32(acc.w);
        *(uint4*)(&As_u[lrow * 68 + cc]) = uu;
        __syncthreads();
    }

    // ---- phase 2: load W, MMA K=64 ----
#pragma unroll
    for (int i = 0; i < 4; i++) {
        int li = tid + i * 256;
        int kr = li >> 4, n4 = li & 15;
        float4 w = *(const float4*)(W + (size_t)kr * 64 + n4 * 4);
        uint4 u;
        u.x = f2tf32(w.x); u.y = f2tf32(w.y); u.z = f2tf32(w.z); u.w = f2tf32(w.w);
        *(uint4*)(&Bs_u[kr * 72 + n4 * 4]) = u;
    }
    __syncthreads();

    int wid = tid >> 5, lane = tid & 31;
    int g = lane >> 2, tig = lane & 3;
    int wr0 = wid * 16;

    float c[8][4];
#pragma unroll
    for (int j = 0; j < 8; j++)
#pragma unroll
        for (int q = 0; q < 4; q++) c[j][q] = 0.f;

#pragma unroll
    for (int s = 0; s < 8; s++) {
        int k8 = s * 8;
        uint32_t x0 = As_u[(wr0 + g) * 68 + k8 + tig];
        uint32_t x1 = As_u[(wr0 + g + 8) * 68 + k8 + tig];
        uint32_t x2 = As_u[(wr0 + g) * 68 + k8 + tig + 4];
        uint32_t x3 = As_u[(wr0 + g + 8) * 68 + k8 + tig + 4];
#pragma unroll
        for (int j = 0; j < 8; j++) {
            uint32_t b0 = Bs_u[(k8 + tig) * 72 + j * 8 + g];
            uint32_t b1 = Bs_u[(k8 + tig + 4) * 72 + j * 8 + g];
            mma_tf32(c[j][0], c[j][1], c[j][2], c[j][3], x0, x1, x2, x3, b0, b1);
        }
    }

    // ---- epilogue: bias, store to tA, stats ----
    int rlo = row0 + wr0 + g;
    int rhi = rlo + 8;
    bool vlo = rlo < NN, vhi = rhi < NN;
#pragma unroll
    for (int j = 0; j < 8; j++) {
        int e0 = j * 8 + 2 * tig;
        float b0 = bias[e0], b1 = bias[e0 + 1];
        float y00 = c[j][0] + b0, y01 = c[j][1] + b1;
        float y10 = c[j][2] + b0, y11 = c[j][3] + b1;
        if (vlo) *(float2*)(g_tA + (size_t)rlo * 64 + e0) = make_float2(y00, y01);
        if (vhi) *(float2*)(g_tA + (size_t)rhi * 64 + e0) = make_float2(y10, y11);
        float s0 = (vlo ? y00 : 0.f) + (vhi ? y10 : 0.f);
        float s1 = (vlo ? y01 : 0.f) + (vhi ? y11 : 0.f);
        float q0 = (vlo ? y00 * y00 : 0.f) + (vhi ? y10 * y10 : 0.f);
        float q1 = (vlo ? y01 * y01 : 0.f) + (vhi ? y11 * y11 : 0.f);
#pragma unroll
        for (int m = 4; m <= 16; m <<= 1) {
            s0 += __shfl_xor_sync(0xffffffffu, s0, m);
            s1 += __shfl_xor_sync(0xffffffffu, s1, m);
            q0 += __shfl_xor_sync(0xffffffffu, q0, m);
            q1 += __shfl_xor_sync(0xffffffffu, q1, m);
        }
        if (g == 0) {
            sw[wid * 128 + e0] = s0;
            sw[wid * 128 + e0 + 1] = s1;
            sw[wid * 128 + 64 + e0] = q0;
            sw[wid * 128 + 64 + e0 + 1] = q1;
        }
    }
    __syncthreads();
    if (tid < 128) {
        float tot = 0.f;
#pragma unroll
        for (int w = 0; w < 8; w++) tot += sw[w * 128 + tid];
        atomicAdd(&stats[tid], tot);
        __threadfence();
    }
    __syncthreads();
    if (tid == 0) {
        int v = atomicAdd(&g_done[sstage], 1);
        slast = (v == (int)gridDim.x - 1);
    }
    __syncthreads();
    if (slast && tid < 64) {
        float s_ = __ldcg(&stats[tid]);
        float q_ = __ldcg(&stats[64 + tid]);
        float m = s_ * (1.f / NN);
        float var = q_ * (1.f / NN) - m * m;
        float a = gamma[tid] * rsqrtf(var + BN_EPS);
        g_ab[sstage * 128 + tid] = a;
        g_ab[sstage * 128 + 64 + tid] = beta[tid] - a * m;
    }
}

// ---------------- final pooling (level NL, no gather) ----------------
__global__ __launch_bounds__(256) void epilogue_kernel(int sstage, int level,
                                                       const int* __restrict__ batch)
{
    __shared__ float4 su[16][17];
    __shared__ int sb[16];
    const float* T = g_tB;
    const float* ab = g_ab + sstage * 128;
    float* pooled_level = g_pooled + (size_t)level * GG * HH;
    int tid = threadIdx.x;
    int rl = tid >> 4, qq = tid & 15;
    int r = blockIdx.x * 16 + rl;
    int cc = qq * 4;
    float4 u = make_float4(0.f, 0.f, 0.f, 0.f);
    int b = -1;
    if (r < NN) {
        float4 v = *(const float4*)(T + (size_t)r * 64 + cc);
        u.x = fmaxf(0.f, ab[cc + 0] * v.x + ab[64 + cc + 0]);
        u.y = fmaxf(0.f, ab[cc + 1] * v.y + ab[64 + cc + 1]);
        u.z = fmaxf(0.f, ab[cc + 2] * v.z + ab[64 + cc + 2]);
        u.w = fmaxf(0.f, ab[cc + 3] * v.w + ab[64 + cc + 3]);
        b = batch[r];
    }
    if (qq == 0) sb[rl] = b;
    su[rl][qq] = u;
    __syncthreads();
    if (r < NN) {
        bool head = (rl == 0) || (b != sb[rl - 1]);
        if (head) {
            float4 acc = u;
            for (int k = rl + 1; k < 16 && sb[k] == b; k++) {
                float4 w = su[k][qq];
                acc.x += w.x; acc.y += w.y; acc.z += w.z; acc.w += w.w;
            }
            red_add_v4(pooled_level + (size_t)b * 64 + cc, acc);
        }
    }
}

// ---------------- readout ----------------
__global__ void final_kernel(const float* __restrict__ linW,
                             const float* __restrict__ linb,
                             float* __restrict__ out)
{
    __shared__ float ps[(NLAYERS + 1) * 64];
    int g = blockIdx.x, t = threadIdx.x;
    for (int i = t; i < (NLAYERS + 1) * 64; i += 64) {
        int l = i >> 6, j = i & 63;
        ps[i] = g_pooled[(size_t)l * GG * 64 + (size_t)g * 64 + j];
    }
    __syncthreads();
    float acc = (float)g_cnt[g] * linb[t];
#pragma unroll
    for (int l = 1; l < NLAYERS + 1; l++) acc += linb[l * 64 + t];
    for (int l = 0; l < NLAYERS + 1; l++) {
        const float* wl = linW + (size_t)l * 64 * 64;
#pragma unroll 8
        for (int j = 0; j < 64; j++)
            acc += ps[l * 64 + j] * wl[j * 64 + t];
    }
    out[(size_t)g * 64 + t] = acc;
}

// ---------------- launch ----------------

extern "C" void kernel_launch(void* const* d_in, const int* in_sizes, int n_in,
                              void* d_out, int out_size)
{
    const float* x     = (const float*)d_in[0];
    const int*   edge  = (const int*)d_in[1];
    const int*   batch = (const int*)d_in[2];
    const float* fW1 = (const float*)d_in[3];
    const float* fb1 = (const float*)d_in[4];
    const float* fg1 = (const float*)d_in[5];
    const float* fbt1= (const float*)d_in[6];
    const float* fW2 = (const float*)d_in[7];
    const float* fb2 = (const float*)d_in[8];
    const float* fg2 = (const float*)d_in[9];
    const float* fbt2= (const float*)d_in[10];
    const float* cW1 = (const float*)d_in[11];
    const float* cb1 = (const float*)d_in[12];
    const float* cg1 = (const float*)d_in[13];
    const float* cbt1= (const float*)d_in[14];
    const float* cW2 = (const float*)d_in[15];
    const float* cb2 = (const float*)d_in[16];
    const float* cg2 = (const float*)d_in[17];
    const float* cbt2= (const float*)d_in[18];
    const float* linW= (const float*)d_in[19];
    const float* linb= (const float*)d_in[20];

    cudaFuncSetAttribute(gin_fused_kernel,
                         cudaFuncAttributeMaxDynamicSharedMemorySize, FS_BYTES);

    const int epi_blocks = (NN + 15) / 16;

    zero_kernel<<<640, 256>>>();
    count_kernel<<<(EE + 255) / 256, 256>>>(edge, batch);
    scan_block_kernel<<<SCAN_NBLK, 1024>>>();
    scan_top_kernel<<<1, 128>>>();
    scan_add_kernel<<<SCAN_NBLK, 1024>>>();
    fill_csr_kernel<<<(EE + 255) / 256, 256>>>(edge);

    // first_h
    gemm_tc_kernel<<<GEMM_BLOCKS, 256>>>(x, 0, FEADIM, fW1, fb1, -1, 0, 0, fg1, fbt1);
    gemm_tc_kernel<<<GEMM_BLOCKS, 256>>>(nullptr, 1, HH, fW2, fb2, 0, 1, 1, fg2, fbt2);

    for (int l = 0; l < NLAYERS; l++) {
        int sA = 2 + 2 * l, sB = 3 + 2 * l;
        int st = 2 * l + 1;
        gin_fused_kernel<<<GEMM_BLOCKS, 256, FS_BYTES>>>(
            st, l, batch, cW1 + (size_t)l * HH * HH, cb1 + (size_t)l * HH,
            sA, cg1 + (size_t)l * HH, cbt1 + (size_t)l * HH);
        gemm_tc_kernel<<<GEMM_BLOCKS, 256>>>(nullptr, 1, HH,
                                             cW2 + (size_t)l * HH * HH, cb2 + (size_t)l * HH,
                                             sA, 1, sB, cg2 + (size_t)l * HH, cbt2 + (size_t)l * HH);
    }
    epilogue_kernel<<<epi_blocks, 256>>>(9, NLAYERS, batch);
    final_kernel<<<GG, 64>>>(linW, linb, (float*)d_out);
}

// round 10
// speedup vs baseline: 1.4125x; 1.1079x over previous
#include <cuda_runtime.h>
#include <cstdint>

#define NN 100000
#define EE 1600000
#define FEADIM 128
#define HH 64
#define GG 512
#define NLAYERS 4
#define BN_EPS 1e-5f
#define SCAN_NBLK 98   // ceil((NN+1)/1024)
#define GEMM_BLOCKS ((NN + 127) / 128)   // 782

// ---------------- scratch ----------------
__device__ float g_tA[(size_t)NN * HH];
__device__ float g_tB[(size_t)NN * HH];
__device__ float g_z[(size_t)NN * HH];
__device__ float g_stats[10 * 128];
__device__ float g_ab[10 * 128];
__device__ float g_pooled[(NLAYERS + 1) * GG * HH];
__device__ int   g_cnt[GG];
__device__ int   g_deg[NN];
__device__ int   g_cur[NN];
__device__ int   g_off[NN + 1];
__device__ int   g_bsum[SCAN_NBLK];
__device__ int   g_csr[EE];
__device__ int   g_done[16];

__device__ __forceinline__ void red_add_v4(float* p, float4 v) {
    asm volatile("red.global.add.v4.f32 [%0], {%1,%2,%3,%4};"
                 :: "l"(p), "f"(v.x), "f"(v.y), "f"(v.z), "f"(v.w) : "memory");
}
__device__ __forceinline__ uint32_t f2tf32(float f) {
    uint32_t r;
    asm("cvt.rna.tf32.f32 %0, %1;" : "=r"(r) : "f"(f));
    return r;
}
__device__ __forceinline__ void mma_tf32(float& c0, float& c1, float& c2, float& c3,
                                         uint32_t a0, uint32_t a1, uint32_t a2, uint32_t a3,
                                         uint32_t b0, uint32_t b1) {
    asm volatile("mma.sync.aligned.m16n8k8.row.col.f32.tf32.tf32.f32 "
                 "{%0,%1,%2,%3}, {%4,%5,%6,%7}, {%8,%9}, {%0,%1,%2,%3};"
                 : "+f"(c0), "+f"(c1), "+f"(c2), "+f"(c3)
                 : "r"(a0), "r"(a1), "r"(a2), "r"(a3), "r"(b0), "r"(b1));
}

// ---------------- setup kernels ----------------

__global__ void zero_kernel() {
    const int TOT = (NLAYERS + 1) * GG * HH;
    for (int i = blockIdx.x * blockDim.x + threadIdx.x; i < TOT;
         i += gridDim.x * blockDim.x) {
        g_pooled[i] = 0.f;
        if (i < NN) { g_deg[i] = 0; g_cur[i] = 0; }
        if (i < 10 * 128) g_stats[i] = 0.f;
        if (i < GG) g_cnt[i] = 0;
        if (i < 16) g_done[i] = 0;
    }
}

__global__ void count_kernel(const int* __restrict__ edge, const int* __restrict__ batch) {
    int i = blockIdx.x * blockDim.x + threadIdx.x;
    if (i < EE) atomicAdd(&g_deg[edge[EE + i]], 1);
    if (i < NN) atomicAdd(&g_cnt[batch[i]], 1);
}

__global__ void scan_block_kernel() {
    __shared__ int s[1024];
    int tid = threadIdx.x;
    int i = blockIdx.x * 1024 + tid;
    int v = (i < NN) ? g_deg[i] : 0;
    s[tid] = v;
    __syncthreads();
    for (int off = 1; off < 1024; off <<= 1) {
        int t = (tid >= off) ? s[tid - off] : 0;
        __syncthreads();
        s[tid] += t;
        __syncthreads();
    }
    if (i <= NN) g_off[i] = s[tid] - v;
    if (tid == 1023) g_bsum[blockIdx.x] = s[1023];
}

// per-block: base = sum of preceding block totals, added to this block's offsets
__global__ void scan_add_kernel() {
    __shared__ int sb[128];
    int tid = threadIdx.x;
    if (tid < 128) sb[tid] = (tid < (int)blockIdx.x && tid < SCAN_NBLK) ? g_bsum[tid] : 0;
    __syncthreads();
    if (tid < 64) sb[tid] += sb[tid + 64];
    __syncthreads();
    if (tid < 32) {
        int v = sb[tid] + sb[tid + 32];
#pragma unroll
        for (int m = 16; m > 0; m >>= 1) v += __shfl_xor_sync(0xffffffffu, v, m);
        if (tid == 0) sb[0] = v;
    }
    __syncthreads();
    int base = sb[0];
    int i = blockIdx.x * 1024 + tid;
    if (i <= NN) g_off[i] += base;
}

__global__ void fill_csr_kernel(const int* __restrict__ edge) {
    int e = blockIdx.x * blockDim.x + threadIdx.x;
    if (e >= EE) return;
    int d = edge[EE + e];
    int pos = g_off[d] + atomicAdd(&g_cur[d], 1);
    g_csr[pos] = edge[e];
}

// ---------------- tf32 GEMM + fused BN stats & finalize ----------------
__global__ __launch_bounds__(256) void gemm_tc_kernel(
    const float* __restrict__ Aext, int Asel, int K,
    const float* __restrict__ W, const float* __restrict__ bias,
    int tstage, int Ysel, int sstage,
    const float* __restrict__ gamma, const float* __restrict__ beta)
{
    const float* A = (Asel == 0) ? Aext : (Asel == 1 ? g_tA : g_z);
    float* Y = (Ysel == 0) ? g_tA : g_tB;
    const float* trans = (tstage >= 0) ? (g_ab + tstage * 128) : nullptr;
    float* stats = g_stats + sstage * 128;

    __shared__ uint32_t As_u[128 * 36];
    __shared__ uint32_t Bs_u[32 * 72];
    __shared__ float    sw[8 * 128];
    __shared__ bool     slast;

    int tid = threadIdx.x;
    int wid = tid >> 5, lane = tid & 31;
    int g = lane >> 2, tig = lane & 3;
    int row0 = blockIdx.x * 128;
    int wr0 = wid * 16;

    float c[8][4];
#pragma unroll
    for (int j = 0; j < 8; j++)
#pragma unroll
        for (int q = 0; q < 4; q++) c[j][q] = 0.f;

    const int nchunk = K >> 5;
    for (int ch = 0; ch < nchunk; ch++) {
        int k0 = ch * 32;
#pragma unroll
        for (int i = 0; i < 4; i++) {
            int li = tid + i * 256;
            int r = li >> 3, c4 = li & 7;
            int grow = row0 + r;
            float4 v = make_float4(0.f, 0.f, 0.f, 0.f);
            if (grow < NN) v = *(const float4*)(A + (size_t)grow * K + k0 + c4 * 4);
            if (trans) {
                int kb = k0 + c4 * 4;
                v.x = fmaxf(0.f, trans[kb + 0] * v.x + trans[64 + kb + 0]);
                v.y = fmaxf(0.f, trans[kb + 1] * v.y + trans[64 + kb + 1]);
                v.z = fmaxf(0.f, trans[kb + 2] * v.z + trans[64 + kb + 2]);
                v.w = fmaxf(0.f, trans[kb + 3] * v.w + trans[64 + kb + 3]);
            }
            uint4 u;
            u.x = f2tf32(v.x); u.y = f2tf32(v.y); u.z = f2tf32(v.z); u.w = f2tf32(v.w);
            *(uint4*)(&As_u[r * 36 + c4 * 4]) = u;
        }
#pragma unroll
        for (int i = 0; i < 2; i++) {
            int li = tid + i * 256;
            int kr = li >> 4, n4 = li & 15;
            float4 w = *(const float4*)(W + (size_t)(k0 + kr) * 64 + n4 * 4);
            uint4 u;
            u.x = f2tf32(w.x); u.y = f2tf32(w.y); u.z = f2tf32(w.z); u.w = f2tf32(w.w);
            *(uint4*)(&Bs_u[kr * 72 + n4 * 4]) = u;
        }
        __syncthreads();
#pragma unroll
        for (int s = 0; s < 4; s++) {
            int k8 = s * 8;
            uint32_t a0 = As_u[(wr0 + g) * 36 + k8 + tig];
            uint32_t a1 = As_u[(wr0 + g + 8) * 36 + k8 + tig];
            uint32_t a2 = As_u[(wr0 + g) * 36 + k8 + tig + 4];
            uint32_t a3 = As_u[(wr0 + g + 8) * 36 + k8 + tig + 4];
#pragma unroll
            for (int j = 0; j < 8; j++) {
                uint32_t b0 = Bs_u[(k8 + tig) * 72 + j * 8 + g];
                uint32_t b1 = Bs_u[(k8 + tig + 4) * 72 + j * 8 + g];
                mma_tf32(c[j][0], c[j][1], c[j][2], c[j][3], a0, a1, a2, a3, b0, b1);
            }
        }
        __syncthreads();
    }

    int rlo = row0 + wr0 + g;
    int rhi = rlo + 8;
    bool vlo = rlo < NN, vhi = rhi < NN;
#pragma unroll
    for (int j = 0; j < 8; j++) {
        int e0 = j * 8 + 2 * tig;
        float b0 = bias[e0], b1 = bias[e0 + 1];
        float y00 = c[j][0] + b0, y01 = c[j][1] + b1;
        float y10 = c[j][2] + b0, y11 = c[j][3] + b1;
        if (vlo) *(float2*)(Y + (size_t)rlo * 64 + e0) = make_float2(y00, y01);
        if (vhi) *(float2*)(Y + (size_t)rhi * 64 + e0) = make_float2(y10, y11);
        float s0 = (vlo ? y00 : 0.f) + (vhi ? y10 : 0.f);
        float s1 = (vlo ? y01 : 0.f) + (vhi ? y11 : 0.f);
        float q0 = (vlo ? y00 * y00 : 0.f) + (vhi ? y10 * y10 : 0.f);
        float q1 = (vlo ? y01 * y01 : 0.f) + (vhi ? y11 * y11 : 0.f);
#pragma unroll
        for (int m = 4; m <= 16; m <<= 1) {
            s0 += __shfl_xor_sync(0xffffffffu, s0, m);
            s1 += __shfl_xor_sync(0xffffffffu, s1, m);
            q0 += __shfl_xor_sync(0xffffffffu, q0, m);
            q1 += __shfl_xor_sync(0xffffffffu, q1, m);
        }
        if (g == 0) {
            sw[wid * 128 + e0] = s0;
            sw[wid * 128 + e0 + 1] = s1;
            sw[wid * 128 + 64 + e0] = q0;
            sw[wid * 128 + 64 + e0 + 1] = q1;
        }
    }
    __syncthreads();
    if (tid < 128) {
        float tot = 0.f;
#pragma unroll
        for (int w = 0; w < 8; w++) tot += sw[w * 128 + tid];
        atomicAdd(&stats[tid], tot);
        __threadfence();
    }
    __syncthreads();
    if (tid == 0) {
        int v = atomicAdd(&g_done[sstage], 1);
        slast = (v == (int)gridDim.x - 1);
    }
    __syncthreads();
    if (slast && tid < 64) {
        float s_ = __ldcg(&stats[tid]);
        float q_ = __ldcg(&stats[64 + tid]);
        float m = s_ * (1.f / NN);
        float var = q_ * (1.f / NN) - m * m;
        float a = gamma[tid] * rsqrtf(var + BN_EPS);
        g_ab[sstage * 128 + tid] = a;
        g_ab[sstage * 128 + 64 + tid] = beta[tid] - a * m;
    }
}

// ---------------- CSR gather + fused level pooling ----------------
// Block = 16 contiguous nodes x 16 lanes. For each node: u = relu(ab∘tB[node]);
// pooled[level] via segmented RED over the 16-node run; z = u + sum relu(ab∘tB[nbr]).
__global__ __launch_bounds__(256) void gather_pool_kernel(int tstage, int level,
                                                          const int* __restrict__ batch)
{
    __shared__ float4 su[16][17];
    __shared__ int sb[16];
    int tid = threadIdx.x;
    int rl = tid >> 4, l16 = tid & 15;
    int cc = l16 * 4;
    int node = blockIdx.x * 16 + rl;          // NN = 6250*16, always valid

    const float* ab = g_ab + tstage * 128;
    float a0 = ab[cc + 0], a1 = ab[cc + 1], a2 = ab[cc + 2], a3 = ab[cc + 3];
    float o0 = ab[64 + cc + 0], o1 = ab[64 + cc + 1], o2 = ab[64 + cc + 2], o3 = ab[64 + cc + 3];
    float* pooled = g_pooled + (size_t)level * GG * HH;

    float4 t = *(const float4*)(g_tB + (size_t)node * 64 + cc);
    float4 u;
    u.x = fmaxf(0.f, a0 * t.x + o0);
    u.y = fmaxf(0.f, a1 * t.y + o1);
    u.z = fmaxf(0.f, a2 * t.z + o2);
    u.w = fmaxf(0.f, a3 * t.w + o3);

    int b = batch[node];
    if (l16 == 0) sb[rl] = b;
    su[rl][l16] = u;
    __syncthreads();
    bool head = (rl == 0) || (b != sb[rl - 1]);
    if (head) {
        float4 acc2 = u;
        for (int k = rl + 1; k < 16 && sb[k] == b; k++) {
            float4 w = su[k][l16];
            acc2.x += w.x; acc2.y += w.y; acc2.z += w.z; acc2.w += w.w;
        }
        red_add_v4(pooled + (size_t)b * 64 + cc, acc2);
    }

    // gather neighbors
    int off0 = g_off[node];
    int cnt = g_off[node + 1] - off0;
    float4 acc = u;
    int vmax = cnt;
#pragma unroll
    for (int sft = 16; sft > 0; sft >>= 1)
        vmax = max(vmax, __shfl_xor_sync(0xffffffffu, vmax, sft));
    for (int base = 0; base < vmax; base += 16) {
        int myidx = (base + l16 < cnt) ? g_csr[off0 + base + l16] : -1;
#pragma unroll
        for (int j = 0; j < 16; j++) {
            int idx = __shfl_sync(0xffffffffu, myidx, j, 16);
            if (idx >= 0) {
                float4 v = *(const float4*)(g_tB + (size_t)idx * 64 + cc);
                acc.x += fmaxf(0.f, a0 * v.x + o0);
                acc.y += fmaxf(0.f, a1 * v.y + o1);
                acc.z += fmaxf(0.f, a2 * v.z + o2);
                acc.w += fmaxf(0.f, a3 * v.w + o3);
            }
        }
    }
    *(float4*)(g_z + (size_t)node * 64 + cc) = acc;
}

// ---------------- pooling only (level NL) ----------------
__global__ __launch_bounds__(256) void epilogue_kernel(int sstage, int level,
                                                       const int* __restrict__ batch)
{
    __shared__ float4 su[16][17];
    __shared__ int sb[16];
    const float* T = g_tB;
    const float* ab = g_ab + sstage * 128;
    float* pooled_level = g_pooled + (size_t)level * GG * HH;
    int tid = threadIdx.x;
    int rl = tid >> 4, qq = tid & 15;
    int r = blockIdx.x * 16 + rl;
    int cc = qq * 4;
    float4 u = make_float4(0.f, 0.f, 0.f, 0.f);
    int b = -1;
    if (r < NN) {
        float4 v = *(const float4*)(T + (size_t)r * 64 + cc);
        u.x = fmaxf(0.f, ab[cc + 0] * v.x + ab[64 + cc + 0]);
        u.y = fmaxf(0.f, ab[cc + 1] * v.y + ab[64 + cc + 1]);
        u.z = fmaxf(0.f, ab[cc + 2] * v.z + ab[64 + cc + 2]);
        u.w = fmaxf(0.f, ab[cc + 3] * v.w + ab[64 + cc + 3]);
        b = batch[r];
    }
    if (qq == 0) sb[rl] = b;
    su[rl][qq] = u;
    __syncthreads();
    if (r < NN) {
        bool head = (rl == 0) || (b != sb[rl - 1]);
        if (head) {
            float4 acc = u;
            for (int k = rl + 1; k < 16 && sb[k] == b; k++) {
                float4 w = su[k][qq];
                acc.x += w.x; acc.y += w.y; acc.z += w.z; acc.w += w.w;
            }
            red_add_v4(pooled_level + (size_t)b * 64 + cc, acc);
        }
    }
}

// ---------------- readout ----------------
__global__ void final_kernel(const float* __restrict__ linW,
                             const float* __restrict__ linb,
                             float* __restrict__ out)
{
    __shared__ float ps[(NLAYERS + 1) * 64];
    int g = blockIdx.x, t = threadIdx.x;
    for (int i = t; i < (NLAYERS + 1) * 64; i += 64) {
        int l = i >> 6, j = i & 63;
        ps[i] = g_pooled[(size_t)l * GG * 64 + (size_t)g * 64 + j];
    }
    __syncthreads();
    float acc = (float)g_cnt[g] * linb[t];
#pragma unroll
    for (int l = 1; l < NLAYERS + 1; l++) acc += linb[l * 64 + t];
    for (int l = 0; l < NLAYERS + 1; l++) {
        const float* wl = linW + (size_t)l * 64 * 64;
#pragma unroll 8
        for (int j = 0; j < 64; j++)
            acc += ps[l * 64 + j] * wl[j * 64 + t];
    }
    out[(size_t)g * 64 + t] = acc;
}

// ---------------- launch ----------------

extern "C" void kernel_launch(void* const* d_in, const int* in_sizes, int n_in,
                              void* d_out, int out_size)
{
    const float* x     = (const float*)d_in[0];
    const int*   edge  = (const int*)d_in[1];
    const int*   batch = (const int*)d_in[2];
    const float* fW1 = (const float*)d_in[3];
    const float* fb1 = (const float*)d_in[4];
    const float* fg1 = (const float*)d_in[5];
    const float* fbt1= (const float*)d_in[6];
    const float* fW2 = (const float*)d_in[7];
    const float* fb2 = (const float*)d_in[8];
    const float* fg2 = (const float*)d_in[9];
    const float* fbt2= (const float*)d_in[10];
    const float* cW1 = (const float*)d_in[11];
    const float* cb1 = (const float*)d_in[12];
    const float* cg1 = (const float*)d_in[13];
    const float* cbt1= (const float*)d_in[14];
    const float* cW2 = (const float*)d_in[15];
    const float* cb2 = (const float*)d_in[16];
    const float* cg2 = (const float*)d_in[17];
    const float* cbt2= (const float*)d_in[18];
    const float* linW= (const float*)d_in[19];
    const float* linb= (const float*)d_in[20];

    const int np_blocks = NN / 16;   // 6250 (exact)

    zero_kernel<<<640, 256>>>();
    count_kernel<<<(EE + 255) / 256, 256>>>(edge, batch);
    scan_block_kernel<<<SCAN_NBLK, 1024>>>();
    scan_add_kernel<<<SCAN_NBLK, 1024>>>();
    fill_csr_kernel<<<(EE + 255) / 256, 256>>>(edge);

    // first_h
    gemm_tc_kernel<<<GEMM_BLOCKS, 256>>>(x, 0, FEADIM, fW1, fb1, -1, 0, 0, fg1, fbt1);
    gemm_tc_kernel<<<GEMM_BLOCKS, 256>>>(nullptr, 1, HH, fW2, fb2, 0, 1, 1, fg2, fbt2);

    for (int l = 0; l < NLAYERS; l++) {
        int sA = 2 + 2 * l, sB = 3 + 2 * l;
        // gather + pool level l (reads tB stage 2l+1)
        gather_pool_kernel<<<np_blocks, 256>>>(2 * l + 1, l, batch);
        gemm_tc_kernel<<<GEMM_BLOCKS, 256>>>(nullptr, 2, HH,
                                             cW1 + (size_t)l * HH * HH, cb1 + (size_t)l * HH,
                                             -1, 0, sA, cg1 + (size_t)l * HH, cbt1 + (size_t)l * HH);
        gemm_tc_kernel<<<GEMM_BLOCKS, 256>>>(nullptr, 1, HH,
                                             cW2 + (size_t)l * HH * HH, cb2 + (size_t)l * HH,
                                             sA, 1, sB, cg2 + (size_t)l * HH, cbt2 + (size_t)l * HH);
    }
    epilogue_kernel<<<np_blocks, 256>>>(9, NLAYERS, batch);
    final_kernel<<<GG, 64>>>(linW, linb, (float*)d_out);
}

// round 11
// speedup vs baseline: 1.4870x; 1.0527x over previous
#include <cuda_runtime.h>
#include <cuda_fp16.h>
#include <cstdint>

#define NN 100000
#define EE 1600000
#define FEADIM 128
#define HH 64
#define GG 512
#define NLAYERS 4
#define BN_EPS 1e-5f
#define SCAN_NBLK 98   // ceil((NN+1)/1024)
#define GEMM_BLOCKS ((NN + 127) / 128)   // 782

// ---------------- scratch ----------------
__device__ float  g_tA[(size_t)NN * HH];
__device__ float  g_tB[(size_t)NN * HH];
__device__ float  g_z[(size_t)NN * HH];
__device__ __half g_h16[(size_t)NN * HH];
__device__ float  g_stats[10 * 128];
__device__ float  g_ab[10 * 128];
__device__ float  g_pooled[(NLAYERS + 1) * GG * HH];
__device__ int    g_cnt[GG];
__device__ int    g_deg[NN];
__device__ int    g_cur[NN];
__device__ int    g_off[NN + 1];
__device__ int    g_bsum[SCAN_NBLK];
__device__ int    g_csr[EE];
__device__ int    g_done[16];

__device__ __forceinline__ void red_add_v4(float* p, float4 v) {
    asm volatile("red.global.add.v4.f32 [%0], {%1,%2,%3,%4};"
                 :: "l"(p), "f"(v.x), "f"(v.y), "f"(v.z), "f"(v.w) : "memory");
}
__device__ __forceinline__ uint32_t f2tf32(float f) {
    uint32_t r;
    asm("cvt.rna.tf32.f32 %0, %1;" : "=r"(r) : "f"(f));
    return r;
}
__device__ __forceinline__ void mma_tf32(float& c0, float& c1, float& c2, float& c3,
                                         uint32_t a0, uint32_t a1, uint32_t a2, uint32_t a3,
                                         uint32_t b0, uint32_t b1) {
    asm volatile("mma.sync.aligned.m16n8k8.row.col.f32.tf32.tf32.f32 "
                 "{%0,%1,%2,%3}, {%4,%5,%6,%7}, {%8,%9}, {%0,%1,%2,%3};"
                 : "+f"(c0), "+f"(c1), "+f"(c2), "+f"(c3)
                 : "r"(a0), "r"(a1), "r"(a2), "r"(a3), "r"(b0), "r"(b1));
}
__device__ __forceinline__ void h8_add(uint4 v, float* a) {
    float2 f;
    f = __half22float2(*(__half2*)&v.x); a[0] += f.x; a[1] += f.y;
    f = __half22float2(*(__half2*)&v.y); a[2] += f.x; a[3] += f.y;
    f = __half22float2(*(__half2*)&v.z); a[4] += f.x; a[5] += f.y;
    f = __half22float2(*(__half2*)&v.w); a[6] += f.x; a[7] += f.y;
}

// ---------------- setup kernels ----------------

__global__ void zero_kernel() {
    const int TOT = (NLAYERS + 1) * GG * HH;
    for (int i = blockIdx.x * blockDim.x + threadIdx.x; i < TOT;
         i += gridDim.x * blockDim.x) {
        g_pooled[i] = 0.f;
        if (i < NN) { g_deg[i] = 0; g_cur[i] = 0; }
        if (i < 10 * 128) g_stats[i] = 0.f;
        if (i < GG) g_cnt[i] = 0;
        if (i < 16) g_done[i] = 0;
    }
}

__global__ void count_kernel(const int* __restrict__ edge, const int* __restrict__ batch) {
    int i = blockIdx.x * blockDim.x + threadIdx.x;
    if (i < EE) atomicAdd(&g_deg[edge[EE + i]], 1);
    if (i < NN) atomicAdd(&g_cnt[batch[i]], 1);
}

__global__ void scan_block_kernel() {
    __shared__ int s[1024];
    int tid = threadIdx.x;
    int i = blockIdx.x * 1024 + tid;
    int v = (i < NN) ? g_deg[i] : 0;
    s[tid] = v;
    __syncthreads();
    for (int off = 1; off < 1024; off <<= 1) {
        int t = (tid >= off) ? s[tid - off] : 0;
        __syncthreads();
        s[tid] += t;
        __syncthreads();
    }
    if (i <= NN) g_off[i] = s[tid] - v;
    if (tid == 1023) g_bsum[blockIdx.x] = s[1023];
}

__global__ void scan_add_kernel() {
    __shared__ int sb[128];
    int tid = threadIdx.x;
    if (tid < 128) sb[tid] = (tid < (int)blockIdx.x && tid < SCAN_NBLK) ? g_bsum[tid] : 0;
    __syncthreads();
    if (tid < 64) sb[tid] += sb[tid + 64];
    __syncthreads();
    if (tid < 32) {
        int v = sb[tid] + sb[tid + 32];
#pragma unroll
        for (int m = 16; m > 0; m >>= 1) v += __shfl_xor_sync(0xffffffffu, v, m);
        if (tid == 0) sb[0] = v;
    }
    __syncthreads();
    int base = sb[0];
    int i = blockIdx.x * 1024 + tid;
    if (i <= NN) g_off[i] += base;
}

__global__ void fill_csr_kernel(const int* __restrict__ edge) {
    int e = blockIdx.x * blockDim.x + threadIdx.x;
    if (e >= EE) return;
    int d = edge[EE + e];
    int pos = g_off[d] + atomicAdd(&g_cur[d], 1);
    g_csr[pos] = edge[e];
}

// ---------------- tf32 GEMM + fused BN stats & finalize ----------------
__global__ __launch_bounds__(256) void gemm_tc_kernel(
    const float* __restrict__ Aext, int Asel, int K,
    const float* __restrict__ W, const float* __restrict__ bias,
    int tstage, int Ysel, int sstage,
    const float* __restrict__ gamma, const float* __restrict__ beta)
{
    const float* A = (Asel == 0) ? Aext : (Asel == 1 ? g_tA : g_z);
    float* Y = (Ysel == 0) ? g_tA : g_tB;
    const float* trans = (tstage >= 0) ? (g_ab + tstage * 128) : nullptr;
    float* stats = g_stats + sstage * 128;

    __shared__ uint32_t As_u[128 * 36];
    __shared__ uint32_t Bs_u[32 * 72];
    __shared__ float    sw[8 * 128];
    __shared__ bool     slast;

    int tid = threadIdx.x;
    int wid = tid >> 5, lane = tid & 31;
    int g = lane >> 2, tig = lane & 3;
    int row0 = blockIdx.x * 128;
    int wr0 = wid * 16;

    float c[8][4];
#pragma unroll
    for (int j = 0; j < 8; j++)
#pragma unroll
        for (int q = 0; q < 4; q++) c[j][q] = 0.f;

    const int nchunk = K >> 5;
    for (int ch = 0; ch < nchunk; ch++) {
        int k0 = ch * 32;
#pragma unroll
        for (int i = 0; i < 4; i++) {
            int li = tid + i * 256;
            int r = li >> 3, c4 = li & 7;
            int grow = row0 + r;
            float4 v = make_float4(0.f, 0.f, 0.f, 0.f);
            if (grow < NN) v = *(const float4*)(A + (size_t)grow * K + k0 + c4 * 4);
            if (trans) {
                int kb = k0 + c4 * 4;
                v.x = fmaxf(0.f, trans[kb + 0] * v.x + trans[64 + kb + 0]);
                v.y = fmaxf(0.f, trans[kb + 1] * v.y + trans[64 + kb + 1]);
                v.z = fmaxf(0.f, trans[kb + 2] * v.z + trans[64 + kb + 2]);
                v.w = fmaxf(0.f, trans[kb + 3] * v.w + trans[64 + kb + 3]);
            }
            uint4 u;
            u.x = f2tf32(v.x); u.y = f2tf32(v.y); u.z = f2tf32(v.z); u.w = f2tf32(v.w);
            *(uint4*)(&As_u[r * 36 + c4 * 4]) = u;
        }
#pragma unroll
        for (int i = 0; i < 2; i++) {
            int li = tid + i * 256;
            int kr = li >> 4, n4 = li & 15;
            float4 w = *(const float4*)(W + (size_t)(k0 + kr) * 64 + n4 * 4);
            uint4 u;
            u.x = f2tf32(w.x); u.y = f2tf32(w.y); u.z = f2tf32(w.z); u.w = f2tf32(w.w);
            *(uint4*)(&Bs_u[kr * 72 + n4 * 4]) = u;
        }
        __syncthreads();
#pragma unroll
        for (int s = 0; s < 4; s++) {
            int k8 = s * 8;
            uint32_t a0 = As_u[(wr0 + g) * 36 + k8 + tig];
            uint32_t a1 = As_u[(wr0 + g + 8) * 36 + k8 + tig];
            uint32_t a2 = As_u[(wr0 + g) * 36 + k8 + tig + 4];
            uint32_t a3 = As_u[(wr0 + g + 8) * 36 + k8 + tig + 4];
#pragma unroll
            for (int j = 0; j < 8; j++) {
                uint32_t b0 = Bs_u[(k8 + tig) * 72 + j * 8 + g];
                uint32_t b1 = Bs_u[(k8 + tig + 4) * 72 + j * 8 + g];
                mma_tf32(c[j][0], c[j][1], c[j][2], c[j][3], a0, a1, a2, a3, b0, b1);
            }
        }
        __syncthreads();
    }

    int rlo = row0 + wr0 + g;
    int rhi = rlo + 8;
    bool vlo = rlo < NN, vhi = rhi < NN;
#pragma unroll
    for (int j = 0; j < 8; j++) {
        int e0 = j * 8 + 2 * tig;
        float b0 = bias[e0], b1 = bias[e0 + 1];
        float y00 = c[j][0] + b0, y01 = c[j][1] + b1;
        float y10 = c[j][2] + b0, y11 = c[j][3] + b1;
        if (vlo) *(float2*)(Y + (size_t)rlo * 64 + e0) = make_float2(y00, y01);
        if (vhi) *(float2*)(Y + (size_t)rhi * 64 + e0) = make_float2(y10, y11);
        float s0 = (vlo ? y00 : 0.f) + (vhi ? y10 : 0.f);
        float s1 = (vlo ? y01 : 0.f) + (vhi ? y11 : 0.f);
        float q0 = (vlo ? y00 * y00 : 0.f) + (vhi ? y10 * y10 : 0.f);
        float q1 = (vlo ? y01 * y01 : 0.f) + (vhi ? y11 * y11 : 0.f);
#pragma unroll
        for (int m = 4; m <= 16; m <<= 1) {
            s0 += __shfl_xor_sync(0xffffffffu, s0, m);
            s1 += __shfl_xor_sync(0xffffffffu, s1, m);
            q0 += __shfl_xor_sync(0xffffffffu, q0, m);
            q1 += __shfl_xor_sync(0xffffffffu, q1, m);
        }
        if (g == 0) {
            sw[wid * 128 + e0] = s0;
            sw[wid * 128 + e0 + 1] = s1;
            sw[wid * 128 + 64 + e0] = q0;
            sw[wid * 128 + 64 + e0 + 1] = q1;
        }
    }
    __syncthreads();
    if (tid < 128) {
        float tot = 0.f;
#pragma unroll
        for (int w = 0; w < 8; w++) tot += sw[w * 128 + tid];
        atomicAdd(&stats[tid], tot);
        __threadfence();
    }
    __syncthreads();
    if (tid == 0) {
        int v = atomicAdd(&g_done[sstage], 1);
        slast = (v == (int)gridDim.x - 1);
    }
    __syncthreads();
    if (slast && tid < 64) {
        float s_ = __ldcg(&stats[tid]);
        float q_ = __ldcg(&stats[64 + tid]);
        float m = s_ * (1.f / NN);
        float var = q_ * (1.f / NN) - m * m;
        float a = gamma[tid] * rsqrtf(var + BN_EPS);
        g_ab[sstage * 128 + tid] = a;
        g_ab[sstage * 128 + 64 + tid] = beta[tid] - a * m;
    }
}

// ---------------- activate + pool (+ optional fp16 h write) ----------------
// u = relu(ab_st ∘ tB); pooled[level] += u (segmented); if write_h: h16 = fp16(u)
__global__ __launch_bounds__(256) void act_pool_kernel(int sstage, int level,
                                                       const int* __restrict__ batch,
                                                       int write_h)
{
    __shared__ float4 su[16][17];
    __shared__ int sb[16];
    const float* ab = g_ab + sstage * 128;
    float* pooled_level = g_pooled + (size_t)level * GG * HH;
    int tid = threadIdx.x;
    int rl = tid >> 4, qq = tid & 15;
    int r = blockIdx.x * 16 + rl;           // NN = 6250*16, always valid
    int cc = qq * 4;

    float4 v = *(const float4*)(g_tB + (size_t)r * 64 + cc);
    float4 u;
    u.x = fmaxf(0.f, ab[cc + 0] * v.x + ab[64 + cc + 0]);
    u.y = fmaxf(0.f, ab[cc + 1] * v.y + ab[64 + cc + 1]);
    u.z = fmaxf(0.f, ab[cc + 2] * v.z + ab[64 + cc + 2]);
    u.w = fmaxf(0.f, ab[cc + 3] * v.w + ab[64 + cc + 3]);
    int b = batch[r];

    if (write_h) {
        __half2 p0 = __floats2half2_rn(u.x, u.y);
        __half2 p1 = __floats2half2_rn(u.z, u.w);
        uint2 pk;
        pk.x = *(uint32_t*)&p0;
        pk.y = *(uint32_t*)&p1;
        ((uint2*)g_h16)[(size_t)r * 16 + qq] = pk;
    }

    if (qq == 0) sb[rl] = b;
    su[rl][qq] = u;
    __syncthreads();
    bool head = (rl == 0) || (b != sb[rl - 1]);
    if (head) {
        float4 acc = u;
        for (int k = rl + 1; k < 16 && sb[k] == b; k++) {
            float4 w = su[k][qq];
            acc.x += w.x; acc.y += w.y; acc.z += w.z; acc.w += w.w;
        }
        red_add_v4(pooled_level + (size_t)b * 64 + cc, acc);
    }
}

// ---------------- fp16 CSR gather: z[i] = h[i] + sum_{j->i} h[j] ----------------
// 8 lanes per node; each lane covers 8 columns (one uint4 = 8 halves per row).
__global__ __launch_bounds__(256) void gather_kernel() {
    int gt = blockIdx.x * 256 + threadIdx.x;
    int node = gt >> 3;                   // grid sized exactly: NN*8/256
    int l8 = threadIdx.x & 7;

    int off0 = g_off[node];
    int cnt = g_off[node + 1] - off0;

    const uint4* hr = (const uint4*)g_h16;
    float acc[8];
#pragma unroll
    for (int i = 0; i < 8; i++) acc[i] = 0.f;
    h8_add(hr[(size_t)node * 8 + l8], acc);

    // warp-uniform bound so width-8 shuffles never diverge across subgroups
    int vmax = cnt;
#pragma unroll
    for (int sft = 16; sft > 0; sft >>= 1)
        vmax = max(vmax, __shfl_xor_sync(0xffffffffu, vmax, sft));

    for (int base = 0; base < vmax; base += 8) {
        int myidx = (base + l8 < cnt) ? g_csr[off0 + base + l8] : -1;
#pragma unroll
        for (int j = 0; j < 8; j++) {
            int idx = __shfl_sync(0xffffffffu, myidx, j, 8);
            if (idx >= 0) h8_add(hr[(size_t)idx * 8 + l8], acc);
        }
    }
    float* zp = g_z + (size_t)node * 64 + l8 * 8;
    *(float4*)zp       = make_float4(acc[0], acc[1], acc[2], acc[3]);
    *(float4*)(zp + 4) = make_float4(acc[4], acc[5], acc[6], acc[7]);
}

// ---------------- readout ----------------
__global__ void final_kernel(const float* __restrict__ linW,
                             const float* __restrict__ linb,
                             float* __restrict__ out)
{
    __shared__ float ps[(NLAYERS + 1) * 64];
    int g = blockIdx.x, t = threadIdx.x;
    for (int i = t; i < (NLAYERS + 1) * 64; i += 64) {
        int l = i >> 6, j = i & 63;
        ps[i] = g_pooled[(size_t)l * GG * 64 + (size_t)g * 64 + j];
    }
    __syncthreads();
    float acc = (float)g_cnt[g] * linb[t];
#pragma unroll
    for (int l = 1; l < NLAYERS + 1; l++) acc += linb[l * 64 + t];
    for (int l = 0; l < NLAYERS + 1; l++) {
        const float* wl = linW + (size_t)l * 64 * 64;
#pragma unroll 8
        for (int j = 0; j < 64; j++)
            acc += ps[l * 64 + j] * wl[j * 64 + t];
    }
    out[(size_t)g * 64 + t] = acc;
}

// ---------------- launch ----------------

extern "C" void kernel_launch(void* const* d_in, const int* in_sizes, int n_in,
                              void* d_out, int out_size)
{
    const float* x     = (const float*)d_in[0];
    const int*   edge  = (const int*)d_in[1];
    const int*   batch = (const int*)d_in[2];
    const float* fW1 = (const float*)d_in[3];
    const float* fb1 = (const float*)d_in[4];
    const float* fg1 = (const float*)d_in[5];
    const float* fbt1= (const float*)d_in[6];
    const float* fW2 = (const float*)d_in[7];
    const float* fb2 = (const float*)d_in[8];
    const float* fg2 = (const float*)d_in[9];
    const float* fbt2= (const float*)d_in[10];
    const float* cW1 = (const float*)d_in[11];
    const float* cb1 = (const float*)d_in[12];
    const float* cg1 = (const float*)d_in[13];
    const float* cbt1= (const float*)d_in[14];
    const float* cW2 = (const float*)d_in[15];
    const float* cb2 = (const float*)d_in[16];
    const float* cg2 = (const float*)d_in[17];
    const float* cbt2= (const float*)d_in[18];
    const float* linW= (const float*)d_in[19];
    const float* linb= (const float*)d_in[20];

    const int ap_blocks  = NN / 16;       // 6250 (exact)
    const int gat_blocks = NN * 8 / 256;  // 3125 (exact)

    zero_kernel<<<640, 256>>>();
    count_kernel<<<(EE + 255) / 256, 256>>>(edge, batch);
    scan_block_kernel<<<SCAN_NBLK, 1024>>>();
    scan_add_kernel<<<SCAN_NBLK, 1024>>>();
    fill_csr_kernel<<<(EE + 255) / 256, 256>>>(edge);

    // first_h
    gemm_tc_kernel<<<GEMM_BLOCKS, 256>>>(x, 0, FEADIM, fW1, fb1, -1, 0, 0, fg1, fbt1);
    gemm_tc_kernel<<<GEMM_BLOCKS, 256>>>(nullptr, 1, HH, fW2, fb2, 0, 1, 1, fg2, fbt2);

    for (int l = 0; l < NLAYERS; l++) {
        int sA = 2 + 2 * l, sB = 3 + 2 * l;
        act_pool_kernel<<<ap_blocks, 256>>>(2 * l + 1, l, batch, 1);
        gather_kernel<<<gat_blocks, 256>>>();
        gemm_tc_kernel<<<GEMM_BLOCKS, 256>>>(nullptr, 2, HH,
                                             cW1 + (size_t)l * HH * HH, cb1 + (size_t)l * HH,
                                             -1, 0, sA, cg1 + (size_t)l * HH, cbt1 + (size_t)l * HH);
        gemm_tc_kernel<<<GEMM_BLOCKS, 256>>>(nullptr, 1, HH,
                                             cW2 + (size_t)l * HH * HH, cb2 + (size_t)l * HH,
                                             sA, 1, sB, cg2 + (size_t)l * HH, cbt2 + (size_t)l * HH);
    }
    act_pool_kernel<<<ap_blocks, 256>>>(9, NLAYERS, batch, 0);
    final_kernel<<<GG, 64>>>(linW, linb, (float*)d_out);
}

// round 12
// speedup vs baseline: 1.5839x; 1.0651x over previous
#include <cuda_runtime.h>
#include <cuda_fp16.h>
#include <cstdint>

#define NN 100000
#define EE 1600000
#define FEADIM 128
#define HH 64
#define GG 512
#define NLAYERS 4
#define BN_EPS 1e-5f
#define SCAN_NBLK 98   // ceil((NN+1)/1024)
#define GEMM_BLOCKS ((NN + 127) / 128)   // 782

// ---------------- scratch (all activations fp16; 10-bit mantissa == tf32) ----------------
__device__ __half g_tA16[(size_t)NN * HH];
__device__ __half g_tB16[(size_t)NN * HH];
__device__ __half g_z16[(size_t)NN * HH];
__device__ __half g_h16[(size_t)NN * HH];
__device__ float  g_stats[10 * 128];
__device__ float  g_ab[10 * 128];
__device__ float  g_pooled[(NLAYERS + 1) * GG * HH];
__device__ int    g_cnt[GG];
__device__ int    g_deg[NN];
__device__ int    g_cur[NN];
__device__ int    g_off[NN + 1];
__device__ int    g_bsum[SCAN_NBLK];
__device__ int    g_csr[EE];
__device__ int    g_done[16];

__device__ __forceinline__ void red_add_v4(float* p, float4 v) {
    asm volatile("red.global.add.v4.f32 [%0], {%1,%2,%3,%4};"
                 :: "l"(p), "f"(v.x), "f"(v.y), "f"(v.z), "f"(v.w) : "memory");
}
__device__ __forceinline__ uint32_t f2tf32(float f) {
    uint32_t r;
    asm("cvt.rna.tf32.f32 %0, %1;" : "=r"(r) : "f"(f));
    return r;
}
__device__ __forceinline__ void mma_tf32(float& c0, float& c1, float& c2, float& c3,
                                         uint32_t a0, uint32_t a1, uint32_t a2, uint32_t a3,
                                         uint32_t b0, uint32_t b1) {
    asm volatile("mma.sync.aligned.m16n8k8.row.col.f32.tf32.tf32.f32 "
                 "{%0,%1,%2,%3}, {%4,%5,%6,%7}, {%8,%9}, {%0,%1,%2,%3};"
                 : "+f"(c0), "+f"(c1), "+f"(c2), "+f"(c3)
                 : "r"(a0), "r"(a1), "r"(a2), "r"(a3), "r"(b0), "r"(b1));
}
__device__ __forceinline__ void h8_add(uint4 v, float* a) {
    float2 f;
    f = __half22float2(*(__half2*)&v.x); a[0] += f.x; a[1] += f.y;
    f = __half22float2(*(__half2*)&v.y); a[2] += f.x; a[3] += f.y;
    f = __half22float2(*(__half2*)&v.z); a[4] += f.x; a[5] += f.y;
    f = __half22float2(*(__half2*)&v.w); a[6] += f.x; a[7] += f.y;
}

// ---------------- setup kernels ----------------

__global__ void zero_kernel() {
    const int TOT = (NLAYERS + 1) * GG * HH;
    for (int i = blockIdx.x * blockDim.x + threadIdx.x; i < TOT;
         i += gridDim.x * blockDim.x) {
        g_pooled[i] = 0.f;
        if (i < NN) { g_deg[i] = 0; g_cur[i] = 0; }
        if (i < 10 * 128) g_stats[i] = 0.f;
        if (i < GG) g_cnt[i] = 0;
        if (i < 16) g_done[i] = 0;
    }
}

__global__ void count_kernel(const int* __restrict__ edge, const int* __restrict__ batch) {
    int i = blockIdx.x * blockDim.x + threadIdx.x;
    if (i < EE) atomicAdd(&g_deg[edge[EE + i]], 1);
    if (i < NN) atomicAdd(&g_cnt[batch[i]], 1);
}

__global__ void scan_block_kernel() {
    __shared__ int s[1024];
    int tid = threadIdx.x;
    int i = blockIdx.x * 1024 + tid;
    int v = (i < NN) ? g_deg[i] : 0;
    s[tid] = v;
    __syncthreads();
    for (int off = 1; off < 1024; off <<= 1) {
        int t = (tid >= off) ? s[tid - off] : 0;
        __syncthreads();
        s[tid] += t;
        __syncthreads();
    }
    if (i <= NN) g_off[i] = s[tid] - v;
    if (tid == 1023) g_bsum[blockIdx.x] = s[1023];
}

__global__ void scan_add_kernel() {
    __shared__ int sb[128];
    int tid = threadIdx.x;
    if (tid < 128) sb[tid] = (tid < (int)blockIdx.x && tid < SCAN_NBLK) ? g_bsum[tid] : 0;
    __syncthreads();
    if (tid < 64) sb[tid] += sb[tid + 64];
    __syncthreads();
    if (tid < 32) {
        int v = sb[tid] + sb[tid + 32];
#pragma unroll
        for (int m = 16; m > 0; m >>= 1) v += __shfl_xor_sync(0xffffffffu, v, m);
        if (tid == 0) sb[0] = v;
    }
    __syncthreads();
    int base = sb[0];
    int i = blockIdx.x * 1024 + tid;
    if (i <= NN) g_off[i] += base;
}

__global__ void fill_csr_kernel(const int* __restrict__ edge) {
    int e = blockIdx.x * blockDim.x + threadIdx.x;
    if (e >= EE) return;
    int d = edge[EE + e];
    int pos = g_off[d] + atomicAdd(&g_cur[d], 1);
    g_csr[pos] = edge[e];
}

// ---------------- tf32 GEMM (fp16 in/out for internal stages) + fused BN ----------------
// Asel: 0 = Aext fp32 (x), 1 = g_tA16, 2 = g_z16.  Ysel: 0 = g_tA16, 1 = g_tB16.
__global__ __launch_bounds__(256) void gemm_tc_kernel(
    const float* __restrict__ Aext, int Asel, int K,
    const float* __restrict__ W, const float* __restrict__ bias,
    int tstage, int Ysel, int sstage,
    const float* __restrict__ gamma, const float* __restrict__ beta)
{
    const __half* Ah = (Asel == 1) ? g_tA16 : g_z16;
    __half* Y = (Ysel == 0) ? g_tA16 : g_tB16;
    const float* trans = (tstage >= 0) ? (g_ab + tstage * 128) : nullptr;
    float* stats = g_stats + sstage * 128;

    __shared__ uint32_t As_u[128 * 36];
    __shared__ uint32_t Bs_u[32 * 72];
    __shared__ float    sw[8 * 128];
    __shared__ bool     slast;

    int tid = threadIdx.x;
    int wid = tid >> 5, lane = tid & 31;
    int g = lane >> 2, tig = lane & 3;
    int row0 = blockIdx.x * 128;
    int wr0 = wid * 16;

    float c[8][4];
#pragma unroll
    for (int j = 0; j < 8; j++)
#pragma unroll
        for (int q = 0; q < 4; q++) c[j][q] = 0.f;

    const int nchunk = K >> 5;
    for (int ch = 0; ch < nchunk; ch++) {
        int k0 = ch * 32;
#pragma unroll
        for (int i = 0; i < 4; i++) {
            int li = tid + i * 256;
            int r = li >> 3, c4 = li & 7;
            int grow = row0 + r;
            float4 v = make_float4(0.f, 0.f, 0.f, 0.f);
            if (grow < NN) {
                if (Asel == 0) {
                    v = *(const float4*)(Aext + (size_t)grow * K + k0 + c4 * 4);
                } else {
                    uint2 p = *(const uint2*)(Ah + (size_t)grow * 64 + k0 + c4 * 4);
                    float2 f0 = __half22float2(*(__half2*)&p.x);
                    float2 f1 = __half22float2(*(__half2*)&p.y);
                    v = make_float4(f0.x, f0.y, f1.x, f1.y);
                }
            }
            if (trans) {
                int kb = k0 + c4 * 4;
                v.x = fmaxf(0.f, trans[kb + 0] * v.x + trans[64 + kb + 0]);
                v.y = fmaxf(0.f, trans[kb + 1] * v.y + trans[64 + kb + 1]);
                v.z = fmaxf(0.f, trans[kb + 2] * v.z + trans[64 + kb + 2]);
                v.w = fmaxf(0.f, trans[kb + 3] * v.w + trans[64 + kb + 3]);
            }
            uint4 u;
            u.x = f2tf32(v.x); u.y = f2tf32(v.y); u.z = f2tf32(v.z); u.w = f2tf32(v.w);
            *(uint4*)(&As_u[r * 36 + c4 * 4]) = u;
        }
#pragma unroll
        for (int i = 0; i < 2; i++) {
            int li = tid + i * 256;
            int kr = li >> 4, n4 = li & 15;
            float4 w = *(const float4*)(W + (size_t)(k0 + kr) * 64 + n4 * 4);
            uint4 u;
            u.x = f2tf32(w.x); u.y = f2tf32(w.y); u.z = f2tf32(w.z); u.w = f2tf32(w.w);
            *(uint4*)(&Bs_u[kr * 72 + n4 * 4]) = u;
        }
        __syncthreads();
#pragma unroll
        for (int s = 0; s < 4; s++) {
            int k8 = s * 8;
            uint32_t a0 = As_u[(wr0 + g) * 36 + k8 + tig];
            uint32_t a1 = As_u[(wr0 + g + 8) * 36 + k8 + tig];
            uint32_t a2 = As_u[(wr0 + g) * 36 + k8 + tig + 4];
            uint32_t a3 = As_u[(wr0 + g + 8) * 36 + k8 + tig + 4];
#pragma unroll
            for (int j = 0; j < 8; j++) {
                uint32_t b0 = Bs_u[(k8 + tig) * 72 + j * 8 + g];
                uint32_t b1 = Bs_u[(k8 + tig + 4) * 72 + j * 8 + g];
                mma_tf32(c[j][0], c[j][1], c[j][2], c[j][3], a0, a1, a2, a3, b0, b1);
            }
        }
        __syncthreads();
    }

    int rlo = row0 + wr0 + g;
    int rhi = rlo + 8;
    bool vlo = rlo < NN, vhi = rhi < NN;
#pragma unroll
    for (int j = 0; j < 8; j++) {
        int e0 = j * 8 + 2 * tig;
        float b0 = bias[e0], b1 = bias[e0 + 1];
        float y00 = c[j][0] + b0, y01 = c[j][1] + b1;
        float y10 = c[j][2] + b0, y11 = c[j][3] + b1;
        if (vlo) *(__half2*)(Y + (size_t)rlo * 64 + e0) = __floats2half2_rn(y00, y01);
        if (vhi) *(__half2*)(Y + (size_t)rhi * 64 + e0) = __floats2half2_rn(y10, y11);
        float s0 = (vlo ? y00 : 0.f) + (vhi ? y10 : 0.f);
        float s1 = (vlo ? y01 : 0.f) + (vhi ? y11 : 0.f);
        float q0 = (vlo ? y00 * y00 : 0.f) + (vhi ? y10 * y10 : 0.f);
        float q1 = (vlo ? y01 * y01 : 0.f) + (vhi ? y11 * y11 : 0.f);
#pragma unroll
        for (int m = 4; m <= 16; m <<= 1) {
            s0 += __shfl_xor_sync(0xffffffffu, s0, m);
            s1 += __shfl_xor_sync(0xffffffffu, s1, m);
            q0 += __shfl_xor_sync(0xffffffffu, q0, m);
            q1 += __shfl_xor_sync(0xffffffffu, q1, m);
        }
        if (g == 0) {
            sw[wid * 128 + e0] = s0;
            sw[wid * 128 + e0 + 1] = s1;
            sw[wid * 128 + 64 + e0] = q0;
            sw[wid * 128 + 64 + e0 + 1] = q1;
        }
    }
    __syncthreads();
    if (tid < 128) {
        float tot = 0.f;
#pragma unroll
        for (int w = 0; w < 8; w++) tot += sw[w * 128 + tid];
        atomicAdd(&stats[tid], tot);
        __threadfence();
    }
    __syncthreads();
    if (tid == 0) {
        int v = atomicAdd(&g_done[sstage], 1);
        slast = (v == (int)gridDim.x - 1);
    }
    __syncthreads();
    if (slast && tid < 64) {
        float s_ = __ldcg(&stats[tid]);
        float q_ = __ldcg(&stats[64 + tid]);
        float m = s_ * (1.f / NN);
        float var = q_ * (1.f / NN) - m * m;
        float a = gamma[tid] * rsqrtf(var + BN_EPS);
        g_ab[sstage * 128 + tid] = a;
        g_ab[sstage * 128 + 64 + tid] = beta[tid] - a * m;
    }
}

// ---------------- activate + pool (+ optional fp16 h write) ----------------
// u = relu(ab_st ∘ tB16); pooled[level] += u (segmented, fp32); if write_h: h16 = fp16(u)
__global__ __launch_bounds__(256) void act_pool_kernel(int sstage, int level,
                                                       const int* __restrict__ batch,
                                                       int write_h)
{
    __shared__ float4 su[16][17];
    __shared__ int sb[16];
    const float* ab = g_ab + sstage * 128;
    float* pooled_level = g_pooled + (size_t)level * GG * HH;
    int tid = threadIdx.x;
    int rl = tid >> 4, qq = tid & 15;
    int r = blockIdx.x * 16 + rl;           // NN = 6250*16, always valid
    int cc = qq * 4;

    uint2 p = ((const uint2*)g_tB16)[(size_t)r * 16 + qq];
    float2 f0 = __half22float2(*(__half2*)&p.x);
    float2 f1 = __half22float2(*(__half2*)&p.y);
    float4 u;
    u.x = fmaxf(0.f, ab[cc + 0] * f0.x + ab[64 + cc + 0]);
    u.y = fmaxf(0.f, ab[cc + 1] * f0.y + ab[64 + cc + 1]);
    u.z = fmaxf(0.f, ab[cc + 2] * f1.x + ab[64 + cc + 2]);
    u.w = fmaxf(0.f, ab[cc + 3] * f1.y + ab[64 + cc + 3]);
    int b = batch[r];

    if (write_h) {
        __half2 p0 = __floats2half2_rn(u.x, u.y);
        __half2 p1 = __floats2half2_rn(u.z, u.w);
        uint2 pk;
        pk.x = *(uint32_t*)&p0;
        pk.y = *(uint32_t*)&p1;
        ((uint2*)g_h16)[(size_t)r * 16 + qq] = pk;
    }

    if (qq == 0) sb[rl] = b;
    su[rl][qq] = u;
    __syncthreads();
    bool head = (rl == 0) || (b != sb[rl - 1]);
    if (head) {
        float4 acc = u;
        for (int k = rl + 1; k < 16 && sb[k] == b; k++) {
            float4 w = su[k][qq];
            acc.x += w.x; acc.y += w.y; acc.z += w.z; acc.w += w.w;
        }
        red_add_v4(pooled_level + (size_t)b * 64 + cc, acc);
    }
}

// ---------------- fp16 CSR gather: z16[i] = h[i] + sum_{j->i} h[j] ----------------
// 8 lanes per node; each lane covers 8 columns (one uint4 = 8 halves per row).
__global__ __launch_bounds__(256) void gather_kernel() {
    int gt = blockIdx.x * 256 + threadIdx.x;
    int node = gt >> 3;                   // grid sized exactly: NN*8/256
    int l8 = threadIdx.x & 7;

    int off0 = g_off[node];
    int cnt = g_off[node + 1] - off0;

    const uint4* hr = (const uint4*)g_h16;
    float acc[8];
#pragma unroll
    for (int i = 0; i < 8; i++) acc[i] = 0.f;
    h8_add(hr[(size_t)node * 8 + l8], acc);

    // warp-uniform bound so width-8 shuffles never diverge across subgroups
    int vmax = cnt;
#pragma unroll
    for (int sft = 16; sft > 0; sft >>= 1)
        vmax = max(vmax, __shfl_xor_sync(0xffffffffu, vmax, sft));

    for (int base = 0; base < vmax; base += 8) {
        int myidx = (base + l8 < cnt) ? g_csr[off0 + base + l8] : -1;
#pragma unroll
        for (int j = 0; j < 8; j++) {
            int idx = __shfl_sync(0xffffffffu, myidx, j, 8);
            if (idx >= 0) h8_add(hr[(size_t)idx * 8 + l8], acc);
        }
    }
    __half2 o0 = __floats2half2_rn(acc[0], acc[1]);
    __half2 o1 = __floats2half2_rn(acc[2], acc[3]);
    __half2 o2 = __floats2half2_rn(acc[4], acc[5]);
    __half2 o3 = __floats2half2_rn(acc[6], acc[7]);
    uint4 pk;
    pk.x = *(uint32_t*)&o0; pk.y = *(uint32_t*)&o1;
    pk.z = *(uint32_t*)&o2; pk.w = *(uint32_t*)&o3;
    ((uint4*)g_z16)[(size_t)node * 8 + l8] = pk;
}

// ---------------- readout ----------------
__global__ void final_kernel(const float* __restrict__ linW,
                             const float* __restrict__ linb,
                             float* __restrict__ out)
{
    __shared__ float ps[(NLAYERS + 1) * 64];
    int g = blockIdx.x, t = threadIdx.x;
    for (int i = t; i < (NLAYERS + 1) * 64; i += 64) {
        int l = i >> 6, j = i & 63;
        ps[i] = g_pooled[(size_t)l * GG * 64 + (size_t)g * 64 + j];
    }
    __syncthreads();
    float acc = (float)g_cnt[g] * linb[t];
#pragma unroll
    for (int l = 1; l < NLAYERS + 1; l++) acc += linb[l * 64 + t];
    for (int l = 0; l < NLAYERS + 1; l++) {
        const float* wl = linW + (size_t)l * 64 * 64;
#pragma unroll 8
        for (int j = 0; j < 64; j++)
            acc += ps[l * 64 + j] * wl[j * 64 + t];
    }
    out[(size_t)g * 64 + t] = acc;
}

// ---------------- launch ----------------

extern "C" void kernel_launch(void* const* d_in, const int* in_sizes, int n_in,
                              void* d_out, int out_size)
{
    const float* x     = (const float*)d_in[0];
    const int*   edge  = (const int*)d_in[1];
    const int*   batch = (const int*)d_in[2];
    const float* fW1 = (const float*)d_in[3];
    const float* fb1 = (const float*)d_in[4];
    const float* fg1 = (const float*)d_in[5];
    const float* fbt1= (const float*)d_in[6];
    const float* fW2 = (const float*)d_in[7];
    const float* fb2 = (const float*)d_in[8];
    const float* fg2 = (const float*)d_in[9];
    const float* fbt2= (const float*)d_in[10];
    const float* cW1 = (const float*)d_in[11];
    const float* cb1 = (const float*)d_in[12];
    const float* cg1 = (const float*)d_in[13];
    const float* cbt1= (const float*)d_in[14];
    const float* cW2 = (const float*)d_in[15];
    const float* cb2 = (const float*)d_in[16];
    const float* cg2 = (const float*)d_in[17];
    const float* cbt2= (const float*)d_in[18];
    const float* linW= (const float*)d_in[19];
    const float* linb= (const float*)d_in[20];

    const int ap_blocks  = NN / 16;       // 6250 (exact)
    const int gat_blocks = NN * 8 / 256;  // 3125 (exact)

    zero_kernel<<<640, 256>>>();
    count_kernel<<<(EE + 255) / 256, 256>>>(edge, batch);
    scan_block_kernel<<<SCAN_NBLK, 1024>>>();
    scan_add_kernel<<<SCAN_NBLK, 1024>>>();
    fill_csr_kernel<<<(EE + 255) / 256, 256>>>(edge);

    // first_h: x(fp32) -> tA16 ; relu(ab0∘tA16) -> tB16
    gemm_tc_kernel<<<GEMM_BLOCKS, 256>>>(x, 0, FEADIM, fW1, fb1, -1, 0, 0, fg1, fbt1);
    gemm_tc_kernel<<<GEMM_BLOCKS, 256>>>(nullptr, 1, HH, fW2, fb2, 0, 1, 1, fg2, fbt2);

    for (int l = 0; l < NLAYERS; l++) {
        int sA = 2 + 2 * l, sB = 3 + 2 * l;
        act_pool_kernel<<<ap_blocks, 256>>>(2 * l + 1, l, batch, 1);
        gather_kernel<<<gat_blocks, 256>>>();
        gemm_tc_kernel<<<GEMM_BLOCKS, 256>>>(nullptr, 2, HH,
                                             cW1 + (size_t)l * HH * HH, cb1 + (size_t)l * HH,
                                             -1, 0, sA, cg1 + (size_t)l * HH, cbt1 + (size_t)l * HH);
        gemm_tc_kernel<<<GEMM_BLOCKS, 256>>>(nullptr, 1, HH,
                                             cW2 + (size_t)l * HH * HH, cb2 + (size_t)l * HH,
                                             sA, 1, sB, cg2 + (size_t)l * HH, cbt2 + (size_t)l * HH);
    }
    act_pool_kernel<<<ap_blocks, 256>>>(9, NLAYERS, batch, 0);
    final_kernel<<<GG, 64>>>(linW, linb, (float*)d_out);
}